// round 11
// baseline (speedup 1.0000x reference)
#include <cuda_runtime.h>
#include <cuda_bf16.h>

#define D 256
#define NC 64
#define NB 64
#define MAXN 4096
#define SPG 16
#define TILE 64
#define NT 512
#define FLAG_EPS 3e-6f

typedef unsigned long long ull;
typedef unsigned int u32;

#define FMA2(acc, a, b) asm("fma.rn.f32x2 %0, %1, %2, %0;" : "+l"(acc) : "l"(a), "l"(b))
#define DUP(d, x)       asm("mov.b64 %0, {%1, %1};" : "=l"(d) : "r"(__float_as_uint(x)))
#define CVTBF2(r, lo, hi) asm("cvt.rn.bf16x2.f32 %0, %1, %2;" : "=r"(r) : "f"(hi), "f"(lo))

#define LDSM4(r0, r1, r2, r3, addr) \
    asm volatile("ldmatrix.sync.aligned.m8n8.x4.shared.b16 {%0,%1,%2,%3}, [%4];" \
                 : "=r"(r0), "=r"(r1), "=r"(r2), "=r"(r3) : "r"(addr))

#define LDSM4T(r0, r1, r2, r3, addr) \
    asm volatile("ldmatrix.sync.aligned.m8n8.x4.trans.shared.b16 {%0,%1,%2,%3}, [%4];" \
                 : "=r"(r0), "=r"(r1), "=r"(r2), "=r"(r3) : "r"(addr))

#define MMA16816(c, a0, a1, a2, a3, b0, b1) \
    asm volatile("mma.sync.aligned.m16n8k16.row.col.f32.bf16.bf16.f32 " \
                 "{%0,%1,%2,%3}, {%4,%5,%6,%7}, {%8,%9}, {%0,%1,%2,%3};" \
                 : "+f"((c)[0]), "+f"((c)[1]), "+f"((c)[2]), "+f"((c)[3]) \
                 : "r"(a0), "r"(a1), "r"(a2), "r"(a3), "r"(b0), "r"(b1))

__device__ int   g_starts[NB + 1];
__device__ float g_Q[NC * D];
__device__ float g_QtT[D * NC];   // [e][c] (fallback)
__device__ float g_QtC[NC * D];   // [c][e] (bf16 conversion source)
__device__ float g_cK[NC];
__device__ float g_P[NB * NC * D];
__device__ float g_sumA[NB * NC];
__device__ float g_H[NB * NC * D];

__device__ __forceinline__ u32 s2u(const void* p) {
    u32 a;
    asm("{ .reg .u64 t; cvta.to.shared.u64 t, %1; cvt.u32.u64 %0, t; }" : "=r"(a) : "l"(p));
    return a;
}

__device__ __forceinline__ void split2(float v0, float v1, u32& hi, u32& lo) {
    CVTBF2(hi, v0, v1);
    float h0 = __uint_as_float(hi << 16);
    float h1 = __uint_as_float(hi & 0xffff0000u);
    CVTBF2(lo, v0 - h0, v1 - h1);
}

// ---------------- meta ----------------
__global__ void k_meta(const void* __restrict__ batch, int n) {
    __shared__ int sh_is32;
    int t = threadIdx.x;
    if (t == 0) {
        long long v = ((const long long*)batch)[n / 4];
        sh_is32 = (v < 0 || v >= NB) ? 1 : 0;
    }
    __syncthreads();
    int is32 = sh_is32;
    int lo = 0, hi = n;
    while (lo < hi) {
        int mid = (lo + hi) >> 1;
        long long bv = is32 ? (long long)((const int*)batch)[mid]
                            : ((const long long*)batch)[mid];
        if (bv < (long long)t) lo = mid + 1; else hi = mid;
    }
    g_starts[t] = lo;
    if (t == 0) g_starts[NB] = n;
}

// ---------------- Q = Qp @ WQ^T + bQ ----------------
__global__ void k_q(const float* __restrict__ Qp, const float* __restrict__ Wq,
                    const float* __restrict__ bq) {
    int c = blockIdx.x, d = threadIdx.x;
    __shared__ float qp[D];
    qp[d] = Qp[c * D + d];
    __syncthreads();
    float a0 = 0.f, a1 = 0.f, a2 = 0.f, a3 = 0.f;
    #pragma unroll 4
    for (int e = 0; e < D; e += 4) {
        a0 = fmaf(qp[e + 0], Wq[d * D + e + 0], a0);
        a1 = fmaf(qp[e + 1], Wq[d * D + e + 1], a1);
        a2 = fmaf(qp[e + 2], Wq[d * D + e + 2], a2);
        a3 = fmaf(qp[e + 3], Wq[d * D + e + 3], a3);
    }
    g_Q[c * D + d] = ((a0 + a1) + (a2 + a3)) + bq[d];
}

// ---------------- Qt[c][e]; cK[c] ----------------
__global__ void k_qt(const float* __restrict__ Wk, const float* __restrict__ bk) {
    int c = blockIdx.x, e = threadIdx.x;
    __shared__ float q[D];
    q[e] = g_Q[c * D + e];
    __syncthreads();
    float a0 = 0.f, a1 = 0.f;
    #pragma unroll 4
    for (int d = 0; d < D; d += 2) {
        a0 = fmaf(q[d + 0], Wk[(d + 0) * D + e], a0);
        a1 = fmaf(q[d + 1], Wk[(d + 1) * D + e], a1);
    }
    float v = a0 + a1;
    g_QtT[e * NC + c] = v;
    g_QtC[c * D + e] = v;
    if (e == 0) {
        float ck = 0.f;
        for (int d = 0; d < D; d++) ck += q[d] * bk[d];
        g_cK[c] = ck;
    }
}

// ---------------- main fused kernel ----------------
// smem floats:
//   XnbfH [0,8192)      bf16-hi x [64n][256e], rows 512B, swz off^((n&7)<<4)
//   XnbfL [8192,16384)
//   QtbfH [16384,24576) bf16-hi Qt [64c][256e], rows 512B
//   QtbfL [24576,32768)
//   As    [32768,36864) f32 pair-swizzled [n][c]: n*64 + 2*((c>>1)^(n&31)) + (c&1)
//   AbfH  [36864,38912) bf16-hi A [64c][64n], rows 128B, SW128
//   AbfL  [38912,40960)
//   cKs 40960, sAcc 41024, flags 41088 (int cnt + 64 entries)
#define SMEM_FLOATS 41216
extern __shared__ float smem[];

__global__ __launch_bounds__(NT, 1) void k_main(const float* __restrict__ x,
                                                float* __restrict__ argout, int has_arg) {
    float* As   = smem + 32768;
    float* cKs  = smem + 40960;
    float* sAcc = smem + 41024;
    int*   flagn = (int*)(smem + 41088);
    int*   flagl = (int*)(smem + 41089);

    int t = threadIdx.x;
    int g = blockIdx.x / SPG, sl = blockIdx.x % SPG;
    int s0 = g_starts[g], s1 = g_starts[g + 1];
    int cnt = s1 - s0;
    int chunk = (cnt + SPG - 1) / SPG;
    int i0 = s0 + sl * chunk;
    int i1 = min(i0 + chunk, s1);
    if (i0 >= i1) return;  // uniform across block

    u32 sb = s2u(smem);
    const u32 xnH = sb, xnL = sb + 32768;
    const u32 qtH = sb + 65536, qtL = sb + 98304;
    const u32 abH = sb + 147456, abL = sb + 155648;

    // init: zero Xnbf, load cK, convert Qt -> split bf16 [c][e]
    for (int r = t; r < 16384; r += NT) ((u32*)smem)[r] = 0u;
    if (t < NC) { cKs[t] = g_cK[t]; sAcc[t] = 0.f; }
    if (t == 0) *flagn = 0;
    for (int r = t; r < NC * (D / 4); r += NT) {
        int c = r >> 6, e4 = r & 63;
        float4 v = *(const float4*)(g_QtC + c * D + 4 * e4);
        u32 h0, l0, h1, l1;
        split2(v.x, v.y, h0, l0);
        split2(v.z, v.w, h1, l1);
        u32 off = c * 512 + ((e4 * 8) ^ ((c & 7) << 4));
        *(uint2*)((char*)smem + (qtH - sb) + off) = make_uint2(h0, h1);
        *(uint2*)((char*)smem + (qtL - sb) + off) = make_uint2(l0, l1);
    }

    const int lane = t & 31;
    const int w    = t >> 5;            // 0..15

    // Phase-B MMA mapping: cw = c-block(16), nw = n-block(16)
    const int cw = w & 3, nw = w >> 2;
    const int pb_arow = 16 * cw + (lane & 7) + 8 * ((lane >> 3) & 1);
    const int pb_ae   = (lane >> 4) & 1;
    const int pb_asw  = (pb_arow & 7) << 4;
    const int pb_brow = 16 * nw + (lane & 7) + 8 * ((lane >> 4) & 1);
    const int pb_be   = (lane >> 3) & 1;
    const int pb_bsw  = (pb_brow & 7) << 4;
    const int wo_c = 16 * cw + (lane >> 2);
    const int wo_n = 16 * nw + 2 * (lane & 3);

    // Phase-D mapping: wr = c-block(16), wc = d-block(64)
    const int wr = w & 3, wc = w >> 2;
    const int a_row = 16 * wr + (lane & 7) + 8 * ((lane >> 3) & 1);
    const int a_hi = lane >> 4;
    const int a_sw = a_row & 7;
    const int pd_ksub = (lane & 7) + 8 * ((lane >> 3) & 1);
    const int pd_dh = (lane >> 4) & 1;

    float acc[8][4];
    #pragma unroll
    for (int nj = 0; nj < 8; nj++)
        #pragma unroll
        for (int q = 0; q < 4; q++) acc[nj][q] = 0.f;

    __syncthreads();

    for (int i = i0; i < i1; i += TILE) {
        int nb = min(TILE, i1 - i);

        // ---- stage: x -> split bf16 Xnbf [n][e] ----
        if (t == 0) *flagn = 0;
        for (int r = t; r < nb * 64; r += NT) {
            int n = r >> 6, e4 = r & 63;
            float4 v = *(const float4*)(x + (size_t)(i + n) * D + 4 * e4);
            u32 h0, l0, h1, l1;
            split2(v.x, v.y, h0, l0);
            split2(v.z, v.w, h1, l1);
            u32 off = n * 512 + ((e4 * 8) ^ ((n & 7) << 4));
            *(uint2*)((char*)smem + off)         = make_uint2(h0, h1);
            *(uint2*)((char*)smem + 32768 + off) = make_uint2(l0, l1);
        }
        __syncthreads();

        // ---- Phase B (tensor): S[16c x 16n] per warp, k = 256 ----
        // 4 independent accumulator chains (ks parity x n-half) + interleaved
        // MMA ordering so no two consecutive MMAs share an accumulator.
        {
            float sc[4][4];
            #pragma unroll
            for (int p = 0; p < 4; p++)
                #pragma unroll
                for (int q = 0; q < 4; q++) sc[p][q] = 0.f;
            #pragma unroll
            for (int ks = 0; ks < 16; ks++) {
                const int pe = (ks & 1) * 2;
                u32 aoff = pb_arow * 512 + ((32 * ks + 16 * pb_ae) ^ pb_asw);
                u32 boff = pb_brow * 512 + ((32 * ks + 16 * pb_be) ^ pb_bsw);
                u32 ah0, ah1, ah2, ah3, al0, al1, al2, al3;
                u32 bh0, bh1, bh2, bh3, bl0, bl1, bl2, bl3;
                LDSM4(ah0, ah1, ah2, ah3, qtH + aoff);
                LDSM4(al0, al1, al2, al3, qtL + aoff);
                LDSM4(bh0, bh1, bh2, bh3, xnH + boff);
                LDSM4(bl0, bl1, bl2, bl3, xnL + boff);
                MMA16816(sc[pe],     ah0, ah1, ah2, ah3, bh0, bh1);
                MMA16816(sc[pe + 1], ah0, ah1, ah2, ah3, bh2, bh3);
                MMA16816(sc[pe],     al0, al1, al2, al3, bh0, bh1);
                MMA16816(sc[pe + 1], al0, al1, al2, al3, bh2, bh3);
                MMA16816(sc[pe],     ah0, ah1, ah2, ah3, bl0, bl1);
                MMA16816(sc[pe + 1], ah0, ah1, ah2, ah3, bl2, bl3);
            }
            float ck0 = cKs[wo_c], ck1 = cKs[wo_c + 8];
            #pragma unroll
            for (int h = 0; h < 2; h++) {
                float v0 = sc[h][0] + sc[h + 2][0];
                float v1 = sc[h][1] + sc[h + 2][1];
                float v2 = sc[h][2] + sc[h + 2][2];
                float v3 = sc[h][3] + sc[h + 2][3];
                int n0 = wo_n + 8 * h;
                int m0 = n0 & 31, m1 = (n0 + 1) & 31;
                As[n0 * 64 + 2 * ((wo_c >> 1) ^ m0) + (wo_c & 1)] = v0 + ck0;
                As[(n0 + 1) * 64 + 2 * ((wo_c >> 1) ^ m1) + (wo_c & 1)] = v1 + ck0;
                int c1 = wo_c + 8;
                As[n0 * 64 + 2 * ((c1 >> 1) ^ m0) + (c1 & 1)] = v2 + ck1;
                As[(n0 + 1) * 64 + 2 * ((c1 >> 1) ^ m1) + (c1 & 1)] = v3 + ck1;
            }
        }
        __syncthreads();

        // ---- Phase C: softmax + argmax + near-tie flagging ----
        #pragma unroll
        for (int r = 0; r < TILE / 16; r++) {
            int node = r * 16 + w;
            if (node < nb) {
                int m = node & 31;
                int off0 = node * NC + 2 * ((lane >> 1) ^ m) + (lane & 1);
                int off1 = node * NC + 2 * (((lane >> 1) + 16) ^ m) + (lane & 1);
                float s0v = As[off0], s1v = As[off1];
                float p0 = s0v * 0.0625f, p1 = s1v * 0.0625f;
                float mx = fmaxf(p0, p1);
                #pragma unroll
                for (int off = 16; off; off >>= 1)
                    mx = fmaxf(mx, __shfl_xor_sync(0xffffffffu, mx, off));
                float e0 = expf(p0 - mx), e1 = expf(p1 - mx);
                float z = e0 + e1;
                #pragma unroll
                for (int off = 16; off; off >>= 1)
                    z += __shfl_xor_sync(0xffffffffu, z, off);
                float av0 = e0 / z, av1 = e1 / z;
                float bv; int bi;
                if (av0 >= av1) { bv = av0; bi = lane; } else { bv = av1; bi = lane + 32; }
                #pragma unroll
                for (int off = 16; off; off >>= 1) {
                    float ov = __shfl_xor_sync(0xffffffffu, bv, off);
                    int   oi = __shfl_xor_sync(0xffffffffu, bi, off);
                    if (ov > bv || (ov == bv && oi < bi)) { bv = ov; bi = oi; }
                }
                As[off0] = av0;
                As[off1] = av1;
                float x0 = (bi == lane) ? -1e30f : av0;
                float x1 = (bi == lane + 32) ? -1e30f : av1;
                float m2 = fmaxf(x0, x1);
                #pragma unroll
                for (int off = 16; off; off >>= 1)
                    m2 = fmaxf(m2, __shfl_xor_sync(0xffffffffu, m2, off));
                if (lane == 0) {
                    if (has_arg) {
                        int pos = (i + node) - s0;
                        argout[(size_t)g * MAXN + pos] = (float)bi;
                    }
                    if (bv - m2 < FLAG_EPS) {
                        int k = atomicAdd(flagn, 1);
                        flagl[k] = node;
                    }
                }
            }
        }
        __syncthreads();

        // ---- fallback: exact argmax for flagged nodes (rare) ----
        int nf = *flagn;
        if (has_arg) {
            for (int f = w; f < nf; f += 16) {
                int node = flagl[f];
                const float* xr = x + (size_t)(i + node) * D;
                float fs0 = 0.f, fs1 = 0.f;
                for (int e = 0; e < D; e++) {
                    float xe = __ldg(xr + e);
                    float2 q = *(const float2*)(g_QtT + e * NC + 2 * lane);
                    fs0 = fmaf(xe, q.x, fs0);
                    fs1 = fmaf(xe, q.y, fs1);
                }
                fs0 += cKs[2 * lane];
                fs1 += cKs[2 * lane + 1];
                float p0 = fs0 * 0.0625f, p1 = fs1 * 0.0625f;
                float mx = fmaxf(p0, p1);
                #pragma unroll
                for (int off = 16; off; off >>= 1)
                    mx = fmaxf(mx, __shfl_xor_sync(0xffffffffu, mx, off));
                float e0 = expf(p0 - mx), e1 = expf(p1 - mx);
                float z = e0 + e1;
                #pragma unroll
                for (int off = 16; off; off >>= 1)
                    z += __shfl_xor_sync(0xffffffffu, z, off);
                float av0 = e0 / z, av1 = e1 / z;
                float bv; int bi;
                if (av0 >= av1) { bv = av0; bi = 2 * lane; } else { bv = av1; bi = 2 * lane + 1; }
                #pragma unroll
                for (int off = 16; off; off >>= 1) {
                    float ov = __shfl_xor_sync(0xffffffffu, bv, off);
                    int   oi = __shfl_xor_sync(0xffffffffu, bi, off);
                    if (ov > bv || (ov == bv && oi < bi)) { bv = ov; bi = oi; }
                }
                if (lane == 0) {
                    int pos = (i + node) - s0;
                    argout[(size_t)g * MAXN + pos] = (float)bi;
                }
            }
        }

        // sumA accumulation (threads < 64)
        if (t < NC) {
            float sa = sAcc[t];
            int gidx = t >> 1, par = t & 1;
            for (int n = 0; n < nb; n++)
                sa += As[n * NC + 2 * (gidx ^ (n & 31)) + par];
            sAcc[t] = sa;
        }

        // ---- convert A -> AbfH/AbfL ([c][n], rows 128B SW128) ----
        {
            int c = t >> 3, n0 = (t & 7) * 8;
            u32 ph[4], pl[4];
            #pragma unroll
            for (int q = 0; q < 4; q++) {
                int na = n0 + 2 * q, nb2 = na + 1;
                float va = (na < nb)  ? As[na * NC + 2 * ((c >> 1) ^ (na & 31)) + (c & 1)] : 0.f;
                float vb = (nb2 < nb) ? As[nb2 * NC + 2 * ((c >> 1) ^ (nb2 & 31)) + (c & 1)] : 0.f;
                split2(va, vb, ph[q], pl[q]);
            }
            u32 so = (c * 128 + n0 * 2);
            so = so ^ ((so >> 3) & 0x70);
            *(uint4*)((char*)smem + (abH - sb) + so) = make_uint4(ph[0], ph[1], ph[2], ph[3]);
            *(uint4*)((char*)smem + (abL - sb) + so) = make_uint4(pl[0], pl[1], pl[2], pl[3]);
        }
        __syncthreads();

        // ---- Phase D (tensor): acc += A[c][n] * X[n][d], interleaved MMA order ----
        #pragma unroll
        for (int ks = 0; ks < 4; ks++) {
            u32 a_off = (a_row << 7) + (((2 * ks + a_hi) ^ a_sw) << 4);
            u32 ah0, ah1, ah2, ah3, al0, al1, al2, al3;
            LDSM4(ah0, ah1, ah2, ah3, abH + a_off);
            LDSM4(al0, al1, al2, al3, abL + a_off);
            int k_row = 16 * ks + pd_ksub;
            u32 bbase = k_row * 512;
            u32 bsw = (k_row & 7) << 4;
            #pragma unroll
            for (int jj = 0; jj < 4; jj++) {
                u32 b_off = bbase + ((128 * wc + 32 * jj + 16 * pd_dh) ^ bsw);
                u32 bh0, bh1, bh2, bh3, bl0, bl1, bl2, bl3;
                LDSM4T(bh0, bh1, bh2, bh3, xnH + b_off);
                LDSM4T(bl0, bl1, bl2, bl3, xnL + b_off);
                MMA16816(acc[2 * jj],     ah0, ah1, ah2, ah3, bh0, bh1);
                MMA16816(acc[2 * jj + 1], ah0, ah1, ah2, ah3, bh2, bh3);
                MMA16816(acc[2 * jj],     al0, al1, al2, al3, bh0, bh1);
                MMA16816(acc[2 * jj + 1], al0, al1, al2, al3, bh2, bh3);
                MMA16816(acc[2 * jj],     ah0, ah1, ah2, ah3, bl0, bl1);
                MMA16816(acc[2 * jj + 1], ah0, ah1, ah2, ah3, bl2, bl3);
            }
        }
        __syncthreads();
    }

    // ---- flush accumulators ----
    {
        float* pgb = g_P + (size_t)g * NC * D;
        int r0 = 16 * wr + (lane >> 2);
        #pragma unroll
        for (int nj = 0; nj < 8; nj++) {
            int col = 64 * wc + 8 * nj + 2 * (lane & 3);
            atomicAdd(pgb + (size_t)r0 * D + col,           acc[nj][0]);
            atomicAdd(pgb + (size_t)r0 * D + col + 1,       acc[nj][1]);
            atomicAdd(pgb + (size_t)(r0 + 8) * D + col,     acc[nj][2]);
            atomicAdd(pgb + (size_t)(r0 + 8) * D + col + 1, acc[nj][3]);
        }
    }
    if (t < NC) atomicAdd(&g_sumA[g * NC + t], sAcc[t]);
}

// ---------------- epilogue GEMMs: register-tiled f32x2 ----------------
#define ASTR 34
template <int MODE>
__global__ __launch_bounds__(256) void k_gemm(const float* __restrict__ Bmat,
                                              const float* __restrict__ bias,
                                              float* __restrict__ Cout) {
    __shared__ float Ash[D * ASTR];
    int t = threadIdx.x;
    int tx = t & 127, ty = t >> 7;
    int r0 = blockIdx.x * 32;
    const float* Amat = (MODE == 0) ? g_P : g_H;

    {   // stage A [32r][256k] -> Ash[k][r]
        int row = t >> 3, k4 = (t & 7) * 4;
        const float* src = Amat + (size_t)(r0 + row) * D + k4;
        #pragma unroll
        for (int it = 0; it < 8; it++) {
            float4 v = *(const float4*)(src + 32 * it);
            int kb = k4 + 32 * it;
            Ash[(kb + 0) * ASTR + row] = v.x;
            Ash[(kb + 1) * ASTR + row] = v.y;
            Ash[(kb + 2) * ASTR + row] = v.z;
            Ash[(kb + 3) * ASTR + row] = v.w;
        }
    }
    __syncthreads();

    int q0 = 2 * tx;
    int rbase = 16 * ty;
    ull acc2[8][2];
    #pragma unroll
    for (int p = 0; p < 8; p++) { acc2[p][0] = 0ull; acc2[p][1] = 0ull; }

    const float* b0p = Bmat + (size_t)q0 * D;
    const float* b1p = Bmat + (size_t)(q0 + 1) * D;
    for (int k = 0; k < D; k += 4) {
        float4 bv0 = *(const float4*)(b0p + k);
        float4 bv1 = *(const float4*)(b1p + k);
        float b0s[4] = {bv0.x, bv0.y, bv0.z, bv0.w};
        float b1s[4] = {bv1.x, bv1.y, bv1.z, bv1.w};
        #pragma unroll
        for (int kk = 0; kk < 4; kk++) {
            ull bd0, bd1;
            DUP(bd0, b0s[kk]);
            DUP(bd1, b1s[kk]);
            const ull* ar = (const ull*)(Ash + (k + kk) * ASTR + rbase);
            #pragma unroll
            for (int p = 0; p < 8; p++) {
                ull av = ar[p];
                FMA2(acc2[p][0], av, bd0);
                FMA2(acc2[p][1], av, bd1);
            }
        }
    }

    float bias0 = bias[q0], bias1 = bias[q0 + 1];
    #pragma unroll
    for (int p = 0; p < 8; p++) {
        int r = r0 + rbase + 2 * p;
        float v00 = __uint_as_float((u32)(acc2[p][0] & 0xffffffffull));
        float v01 = __uint_as_float((u32)(acc2[p][1] & 0xffffffffull));
        float v10 = __uint_as_float((u32)(acc2[p][0] >> 32));
        float v11 = __uint_as_float((u32)(acc2[p][1] >> 32));
        if (MODE == 0) {
            int c0 = r & (NC - 1), c1 = (r + 1) & (NC - 1);
            float sa0 = g_sumA[r], sa1 = g_sumA[r + 1];
            v00 += g_Q[c0 * D + q0]     + sa0 * bias0;
            v01 += g_Q[c0 * D + q0 + 1] + sa0 * bias1;
            v10 += g_Q[c1 * D + q0]     + sa1 * bias0;
            v11 += g_Q[c1 * D + q0 + 1] + sa1 * bias1;
            *(float2*)(g_H + (size_t)r * D + q0)       = make_float2(v00, v01);
            *(float2*)(g_H + (size_t)(r + 1) * D + q0) = make_float2(v10, v11);
        } else {
            v00 = fmaxf(v00 + bias0, 0.f);
            v01 = fmaxf(v01 + bias1, 0.f);
            v10 = fmaxf(v10 + bias0, 0.f);
            v11 = fmaxf(v11 + bias1, 0.f);
            *(float2*)(Cout + (size_t)r * D + q0)       = make_float2(v00, v01);
            *(float2*)(Cout + (size_t)(r + 1) * D + q0) = make_float2(v10, v11);
        }
    }
}

// ---------------- mask output ----------------
__global__ void k_mask(float* __restrict__ maskout) {
    int idx = blockIdx.x * blockDim.x + threadIdx.x;
    if (idx >= NB * MAXN) return;
    int b = idx >> 12, pos = idx & (MAXN - 1);
    int cnt = g_starts[b + 1] - g_starts[b];
    maskout[idx] = (pos < cnt) ? 1.f : 0.f;
}

extern "C" void kernel_launch(void* const* d_in, const int* in_sizes, int n_in,
                              void* d_out, int out_size) {
    const float* x    = (const float*)d_in[0];
    const void*  bat  = d_in[1];
    const float* Qp   = (const float*)d_in[2];
    const float* WQ_w = (const float*)d_in[3];
    const float* WQ_b = (const float*)d_in[4];
    const float* WK_w = (const float*)d_in[5];
    const float* WK_b = (const float*)d_in[6];
    const float* WV_w = (const float*)d_in[7];
    const float* WV_b = (const float*)d_in[8];
    const float* WO_w = (const float*)d_in[9];
    const float* WO_b = (const float*)d_in[10];
    (void)n_in;

    int n_nodes = in_sizes[0] / D;
    float* out = (float*)d_out;
    int has_arg  = out_size >= (NB * NC * D + NB * MAXN);
    int has_mask = out_size >= (NB * NC * D + 2 * NB * MAXN);
    float* argout  = out + NB * NC * D;
    float* maskout = argout + NB * MAXN;

    void *pP = nullptr, *pS = nullptr;
    cudaGetSymbolAddress(&pP, g_P);
    cudaGetSymbolAddress(&pS, g_sumA);
    cudaMemsetAsync(pP, 0, sizeof(float) * NB * NC * D, 0);
    cudaMemsetAsync(pS, 0, sizeof(float) * NB * NC, 0);
    if (has_arg) cudaMemsetAsync(argout, 0, sizeof(float) * NB * MAXN, 0);

    k_meta<<<1, NB>>>(bat, n_nodes);
    k_q<<<NC, 256>>>(Qp, WQ_w, WQ_b);
    k_qt<<<NC, 256>>>(WK_w, WK_b);

    const int smem_main = SMEM_FLOATS * (int)sizeof(float);
    cudaFuncSetAttribute(k_main, cudaFuncAttributeMaxDynamicSharedMemorySize, smem_main);
    k_main<<<NB * SPG, NT, smem_main>>>(x, argout, has_arg);

    k_gemm<0><<<(NB * NC) / 32, 256>>>(WV_w, WV_b, nullptr);
    k_gemm<1><<<(NB * NC) / 32, 256>>>(WO_w, WO_b, out);

    if (has_mask) k_mask<<<(NB * MAXN) / 256, 256>>>(maskout);
}

// round 12
// speedup vs baseline: 1.0620x; 1.0620x over previous
#include <cuda_runtime.h>
#include <cuda_bf16.h>

#define D 256
#define NC 64
#define NB 64
#define MAXN 4096
#define SPG 16
#define TILE 64
#define NT 512
#define FLAG_EPS 3e-6f

typedef unsigned long long ull;
typedef unsigned int u32;

#define FMA2(acc, a, b) asm("fma.rn.f32x2 %0, %1, %2, %0;" : "+l"(acc) : "l"(a), "l"(b))
#define DUP(d, x)       asm("mov.b64 %0, {%1, %1};" : "=l"(d) : "r"(__float_as_uint(x)))
#define CVTBF2(r, lo, hi) asm("cvt.rn.bf16x2.f32 %0, %1, %2;" : "=r"(r) : "f"(hi), "f"(lo))

#define CP16(dst, src) \
    asm volatile("cp.async.cg.shared.global [%0], [%1], 16;" :: "r"(dst), "l"(src))
#define CPCOMMIT() asm volatile("cp.async.commit_group;" ::: "memory")
#define CPWAIT0()  asm volatile("cp.async.wait_group 0;" ::: "memory")

#define LDSM4(r0, r1, r2, r3, addr) \
    asm volatile("ldmatrix.sync.aligned.m8n8.x4.shared.b16 {%0,%1,%2,%3}, [%4];" \
                 : "=r"(r0), "=r"(r1), "=r"(r2), "=r"(r3) : "r"(addr))

#define LDSM4T(r0, r1, r2, r3, addr) \
    asm volatile("ldmatrix.sync.aligned.m8n8.x4.trans.shared.b16 {%0,%1,%2,%3}, [%4];" \
                 : "=r"(r0), "=r"(r1), "=r"(r2), "=r"(r3) : "r"(addr))

#define MMA16816(c, a0, a1, a2, a3, b0, b1) \
    asm volatile("mma.sync.aligned.m16n8k16.row.col.f32.bf16.bf16.f32 " \
                 "{%0,%1,%2,%3}, {%4,%5,%6,%7}, {%8,%9}, {%0,%1,%2,%3};" \
                 : "+f"((c)[0]), "+f"((c)[1]), "+f"((c)[2]), "+f"((c)[3]) \
                 : "r"(a0), "r"(a1), "r"(a2), "r"(a3), "r"(b0), "r"(b1))

__device__ int   g_starts[NB + 1];
__device__ float g_Q[NC * D];
__device__ float g_QtT[D * NC];   // [e][c] (fallback)
__device__ float g_QtC[NC * D];   // [c][e] (bf16 conversion source)
__device__ float g_cK[NC];
__device__ float g_P[NB * NC * D];
__device__ float g_sumA[NB * NC];
__device__ float g_H[NB * NC * D];

__device__ __forceinline__ u32 s2u(const void* p) {
    u32 a;
    asm("{ .reg .u64 t; cvta.to.shared.u64 t, %1; cvt.u32.u64 %0, t; }" : "=r"(a) : "l"(p));
    return a;
}

__device__ __forceinline__ void split2(float v0, float v1, u32& hi, u32& lo) {
    CVTBF2(hi, v0, v1);
    float h0 = __uint_as_float(hi << 16);
    float h1 = __uint_as_float(hi & 0xffff0000u);
    CVTBF2(lo, v0 - h0, v1 - h1);
}

// ---------------- meta ----------------
__global__ void k_meta(const void* __restrict__ batch, int n) {
    __shared__ int sh_is32;
    int t = threadIdx.x;
    if (t == 0) {
        long long v = ((const long long*)batch)[n / 4];
        sh_is32 = (v < 0 || v >= NB) ? 1 : 0;
    }
    __syncthreads();
    int is32 = sh_is32;
    int lo = 0, hi = n;
    while (lo < hi) {
        int mid = (lo + hi) >> 1;
        long long bv = is32 ? (long long)((const int*)batch)[mid]
                            : ((const long long*)batch)[mid];
        if (bv < (long long)t) lo = mid + 1; else hi = mid;
    }
    g_starts[t] = lo;
    if (t == 0) g_starts[NB] = n;
}

// ---------------- Q = Qp @ WQ^T + bQ ----------------
__global__ void k_q(const float* __restrict__ Qp, const float* __restrict__ Wq,
                    const float* __restrict__ bq) {
    int c = blockIdx.x, d = threadIdx.x;
    __shared__ float qp[D];
    qp[d] = Qp[c * D + d];
    __syncthreads();
    float a0 = 0.f, a1 = 0.f, a2 = 0.f, a3 = 0.f;
    #pragma unroll 4
    for (int e = 0; e < D; e += 4) {
        a0 = fmaf(qp[e + 0], Wq[d * D + e + 0], a0);
        a1 = fmaf(qp[e + 1], Wq[d * D + e + 1], a1);
        a2 = fmaf(qp[e + 2], Wq[d * D + e + 2], a2);
        a3 = fmaf(qp[e + 3], Wq[d * D + e + 3], a3);
    }
    g_Q[c * D + d] = ((a0 + a1) + (a2 + a3)) + bq[d];
}

// ---------------- Qt[c][e]; cK[c] ----------------
__global__ void k_qt(const float* __restrict__ Wk, const float* __restrict__ bk) {
    int c = blockIdx.x, e = threadIdx.x;
    __shared__ float q[D];
    q[e] = g_Q[c * D + e];
    __syncthreads();
    float a0 = 0.f, a1 = 0.f;
    #pragma unroll 4
    for (int d = 0; d < D; d += 2) {
        a0 = fmaf(q[d + 0], Wk[(d + 0) * D + e], a0);
        a1 = fmaf(q[d + 1], Wk[(d + 1) * D + e], a1);
    }
    float v = a0 + a1;
    g_QtT[e * NC + c] = v;
    g_QtC[c * D + e] = v;
    if (e == 0) {
        float ck = 0.f;
        for (int d = 0; d < D; d++) ck += q[d] * bk[d];
        g_cK[c] = ck;
    }
}

// ---------------- main fused kernel ----------------
// smem floats:
//   XnbfH [0,8192)      bf16-hi x [64n][256e], rows 512B, swz off^((n&7)<<4)
//   XnbfL [8192,16384)
//   QtbfH [16384,24576) bf16-hi Qt [64c][256e], rows 512B
//   QtbfL [24576,32768)
//   As    [32768,36864) f32 pair-swizzled [n][c]: n*64 + 2*((c>>1)^(n&31)) + (c&1)
//   AbfH  [36864,38912) bf16-hi A [64c][64n], rows 128B, SW128
//   AbfL  [38912,40960)
//   cKs 40960, sAcc 41024, flags 41088
//   raw   [41216, 57600) f32 staging [64n][256e] linear (cp.async target)
#define SMEM_FLOATS 57600
extern __shared__ float smem[];

__global__ __launch_bounds__(NT, 1) void k_main(const float* __restrict__ x,
                                                float* __restrict__ argout, int has_arg) {
    float* As   = smem + 32768;
    float* cKs  = smem + 40960;
    float* sAcc = smem + 41024;
    int*   flagn = (int*)(smem + 41088);
    int*   flagl = (int*)(smem + 41089);
    float* rawF = smem + 41216;

    int t = threadIdx.x;
    int g = blockIdx.x / SPG, sl = blockIdx.x % SPG;
    int s0 = g_starts[g], s1 = g_starts[g + 1];
    int cnt = s1 - s0;
    int chunk = (cnt + SPG - 1) / SPG;
    int i0 = s0 + sl * chunk;
    int i1 = min(i0 + chunk, s1);
    if (i0 >= i1) return;  // uniform across block

    u32 sb = s2u(smem);
    const u32 xnH = sb, xnL = sb + 32768;
    const u32 qtH = sb + 65536, qtL = sb + 98304;
    const u32 abH = sb + 147456, abL = sb + 155648;
    const u32 rawU = sb + 41216u * 4u;

    // prologue: prefetch first tile into raw staging
    {
        int nbj = min(TILE, i1 - i0);
        for (int r = t; r < nbj * 64; r += NT) {
            int n = r >> 6, e4 = r & 63;
            CP16(rawU + (u32)r * 16u, x + (size_t)(i0 + n) * D + 4 * e4);
        }
        CPCOMMIT();
    }

    // init: zero Xnbf, load cK, convert Qt -> split bf16 [c][e]
    for (int r = t; r < 16384; r += NT) ((u32*)smem)[r] = 0u;
    if (t < NC) { cKs[t] = g_cK[t]; sAcc[t] = 0.f; }
    if (t == 0) *flagn = 0;
    for (int r = t; r < NC * (D / 4); r += NT) {
        int c = r >> 6, e4 = r & 63;
        float4 v = *(const float4*)(g_QtC + c * D + 4 * e4);
        u32 h0, l0, h1, l1;
        split2(v.x, v.y, h0, l0);
        split2(v.z, v.w, h1, l1);
        u32 off = c * 512 + ((e4 * 8) ^ ((c & 7) << 4));
        *(uint2*)((char*)smem + (qtH - sb) + off) = make_uint2(h0, h1);
        *(uint2*)((char*)smem + (qtL - sb) + off) = make_uint2(l0, l1);
    }

    const int lane = t & 31;
    const int w    = t >> 5;            // 0..15

    // Phase-B MMA mapping: cw = c-block(16), nw = n-block(16)
    const int cw = w & 3, nw = w >> 2;
    const int pb_arow = 16 * cw + (lane & 7) + 8 * ((lane >> 3) & 1);
    const int pb_ae   = (lane >> 4) & 1;
    const int pb_asw  = (pb_arow & 7) << 4;
    const int pb_brow = 16 * nw + (lane & 7) + 8 * ((lane >> 4) & 1);
    const int pb_be   = (lane >> 3) & 1;
    const int pb_bsw  = (pb_brow & 7) << 4;
    const int wo_c = 16 * cw + (lane >> 2);
    const int wo_n = 16 * nw + 2 * (lane & 3);

    // Phase-D mapping: wr = c-block(16), wc = d-block(64)
    const int wr = w & 3, wc = w >> 2;
    const int a_row = 16 * wr + (lane & 7) + 8 * ((lane >> 3) & 1);
    const int a_hi = lane >> 4;
    const int a_sw = a_row & 7;
    const int pd_ksub = (lane & 7) + 8 * ((lane >> 3) & 1);
    const int pd_dh = (lane >> 4) & 1;

    float acc[8][4];
    #pragma unroll
    for (int nj = 0; nj < 8; nj++)
        #pragma unroll
        for (int q = 0; q < 4; q++) acc[nj][q] = 0.f;

    __syncthreads();

    for (int i = i0; i < i1; i += TILE) {
        int nb = min(TILE, i1 - i);

        // ---- wait prefetch, convert raw -> split bf16 Xnbf [n][e] ----
        CPWAIT0();
        __syncthreads();
        if (t == 0) *flagn = 0;
        for (int r = t; r < nb * 64; r += NT) {
            int n = r >> 6, e4 = r & 63;
            float4 v = *(const float4*)(rawF + (size_t)r * 4);
            u32 h0, l0, h1, l1;
            split2(v.x, v.y, h0, l0);
            split2(v.z, v.w, h1, l1);
            u32 off = n * 512 + ((e4 * 8) ^ ((n & 7) << 4));
            *(uint2*)((char*)smem + off)         = make_uint2(h0, h1);
            *(uint2*)((char*)smem + 32768 + off) = make_uint2(l0, l1);
        }
        __syncthreads();   // Xn ready AND raw fully consumed

        // ---- prefetch next tile into raw (overlaps B/C/D) ----
        if (i + TILE < i1) {
            int j = i + TILE;
            int nbj = min(TILE, i1 - j);
            for (int r = t; r < nbj * 64; r += NT) {
                int n = r >> 6, e4 = r & 63;
                CP16(rawU + (u32)r * 16u, x + (size_t)(j + n) * D + 4 * e4);
            }
            CPCOMMIT();
        }

        // ---- Phase B (tensor): S[16c x 16n] per warp, k = 256 ----
        {
            float sc[4][4];
            #pragma unroll
            for (int p = 0; p < 4; p++)
                #pragma unroll
                for (int q = 0; q < 4; q++) sc[p][q] = 0.f;
            #pragma unroll
            for (int ks = 0; ks < 16; ks++) {
                const int pe = (ks & 1) * 2;
                u32 aoff = pb_arow * 512 + ((32 * ks + 16 * pb_ae) ^ pb_asw);
                u32 boff = pb_brow * 512 + ((32 * ks + 16 * pb_be) ^ pb_bsw);
                u32 ah0, ah1, ah2, ah3, al0, al1, al2, al3;
                u32 bh0, bh1, bh2, bh3, bl0, bl1, bl2, bl3;
                LDSM4(ah0, ah1, ah2, ah3, qtH + aoff);
                LDSM4(al0, al1, al2, al3, qtL + aoff);
                LDSM4(bh0, bh1, bh2, bh3, xnH + boff);
                LDSM4(bl0, bl1, bl2, bl3, xnL + boff);
                MMA16816(sc[pe],     ah0, ah1, ah2, ah3, bh0, bh1);
                MMA16816(sc[pe + 1], ah0, ah1, ah2, ah3, bh2, bh3);
                MMA16816(sc[pe],     al0, al1, al2, al3, bh0, bh1);
                MMA16816(sc[pe + 1], al0, al1, al2, al3, bh2, bh3);
                MMA16816(sc[pe],     ah0, ah1, ah2, ah3, bl0, bl1);
                MMA16816(sc[pe + 1], ah0, ah1, ah2, ah3, bl2, bl3);
            }
            float ck0 = cKs[wo_c], ck1 = cKs[wo_c + 8];
            #pragma unroll
            for (int h = 0; h < 2; h++) {
                float v0 = sc[h][0] + sc[h + 2][0];
                float v1 = sc[h][1] + sc[h + 2][1];
                float v2 = sc[h][2] + sc[h + 2][2];
                float v3 = sc[h][3] + sc[h + 2][3];
                int n0 = wo_n + 8 * h;
                int m0 = n0 & 31, m1 = (n0 + 1) & 31;
                As[n0 * 64 + 2 * ((wo_c >> 1) ^ m0) + (wo_c & 1)] = v0 + ck0;
                As[(n0 + 1) * 64 + 2 * ((wo_c >> 1) ^ m1) + (wo_c & 1)] = v1 + ck0;
                int c1 = wo_c + 8;
                As[n0 * 64 + 2 * ((c1 >> 1) ^ m0) + (c1 & 1)] = v2 + ck1;
                As[(n0 + 1) * 64 + 2 * ((c1 >> 1) ^ m1) + (c1 & 1)] = v3 + ck1;
            }
        }
        __syncthreads();

        // ---- Phase C: softmax + argmax, 2 nodes per warp interleaved ----
        #pragma unroll
        for (int r = 0; r < 2; r++) {
            int nA = 32 * r + w, nB = nA + 16;
            if (nA >= nb) break;                     // warp-uniform
            bool aB = nB < nb;                       // warp-uniform
            int mA_ = nA & 31, mB_ = nB & 31;
            int offA0 = nA * NC + 2 * ((lane >> 1) ^ mA_) + (lane & 1);
            int offA1 = nA * NC + 2 * (((lane >> 1) + 16) ^ mA_) + (lane & 1);
            int offB0 = nB * NC + 2 * ((lane >> 1) ^ mB_) + (lane & 1);
            int offB1 = nB * NC + 2 * (((lane >> 1) + 16) ^ mB_) + (lane & 1);
            float pA0 = As[offA0] * 0.0625f, pA1 = As[offA1] * 0.0625f;
            float pB0 = aB ? As[offB0] * 0.0625f : 0.f;
            float pB1 = aB ? As[offB1] * 0.0625f : 0.f;
            float mxA = fmaxf(pA0, pA1), mxB = fmaxf(pB0, pB1);
            #pragma unroll
            for (int off = 16; off; off >>= 1) {
                mxA = fmaxf(mxA, __shfl_xor_sync(0xffffffffu, mxA, off));
                mxB = fmaxf(mxB, __shfl_xor_sync(0xffffffffu, mxB, off));
            }
            float eA0 = expf(pA0 - mxA), eA1 = expf(pA1 - mxA);
            float eB0 = expf(pB0 - mxB), eB1 = expf(pB1 - mxB);
            float zA = eA0 + eA1, zB = eB0 + eB1;
            #pragma unroll
            for (int off = 16; off; off >>= 1) {
                zA += __shfl_xor_sync(0xffffffffu, zA, off);
                zB += __shfl_xor_sync(0xffffffffu, zB, off);
            }
            float avA0 = eA0 / zA, avA1 = eA1 / zA;
            float avB0 = eB0 / zB, avB1 = eB1 / zB;
            float bvA; int biA;
            if (avA0 >= avA1) { bvA = avA0; biA = lane; } else { bvA = avA1; biA = lane + 32; }
            float bvB; int biB;
            if (avB0 >= avB1) { bvB = avB0; biB = lane; } else { bvB = avB1; biB = lane + 32; }
            #pragma unroll
            for (int off = 16; off; off >>= 1) {
                float ovA = __shfl_xor_sync(0xffffffffu, bvA, off);
                int   oiA = __shfl_xor_sync(0xffffffffu, biA, off);
                float ovB = __shfl_xor_sync(0xffffffffu, bvB, off);
                int   oiB = __shfl_xor_sync(0xffffffffu, biB, off);
                if (ovA > bvA || (ovA == bvA && oiA < biA)) { bvA = ovA; biA = oiA; }
                if (ovB > bvB || (ovB == bvB && oiB < biB)) { bvB = ovB; biB = oiB; }
            }
            As[offA0] = avA0;
            As[offA1] = avA1;
            if (aB) { As[offB0] = avB0; As[offB1] = avB1; }
            // second best (excluding winner), interleaved
            float xA0 = (biA == lane) ? -1e30f : avA0;
            float xA1 = (biA == lane + 32) ? -1e30f : avA1;
            float xB0 = (biB == lane) ? -1e30f : avB0;
            float xB1 = (biB == lane + 32) ? -1e30f : avB1;
            float m2A = fmaxf(xA0, xA1), m2B = fmaxf(xB0, xB1);
            #pragma unroll
            for (int off = 16; off; off >>= 1) {
                m2A = fmaxf(m2A, __shfl_xor_sync(0xffffffffu, m2A, off));
                m2B = fmaxf(m2B, __shfl_xor_sync(0xffffffffu, m2B, off));
            }
            if (lane == 0) {
                if (has_arg) {
                    int posA = (i + nA) - s0;
                    argout[(size_t)g * MAXN + posA] = (float)biA;
                    if (aB) {
                        int posB = (i + nB) - s0;
                        argout[(size_t)g * MAXN + posB] = (float)biB;
                    }
                }
                if (bvA - m2A < FLAG_EPS) { int k = atomicAdd(flagn, 1); flagl[k] = nA; }
                if (aB && (bvB - m2B < FLAG_EPS)) { int k = atomicAdd(flagn, 1); flagl[k] = nB; }
            }
        }
        __syncthreads();

        // ---- fallback: exact argmax for flagged nodes (rare) ----
        int nf = *flagn;
        if (has_arg) {
            for (int f = w; f < nf; f += 16) {
                int node = flagl[f];
                const float* xr = x + (size_t)(i + node) * D;
                float fs0 = 0.f, fs1 = 0.f;
                for (int e = 0; e < D; e++) {
                    float xe = __ldg(xr + e);
                    float2 q = *(const float2*)(g_QtT + e * NC + 2 * lane);
                    fs0 = fmaf(xe, q.x, fs0);
                    fs1 = fmaf(xe, q.y, fs1);
                }
                fs0 += cKs[2 * lane];
                fs1 += cKs[2 * lane + 1];
                float p0 = fs0 * 0.0625f, p1 = fs1 * 0.0625f;
                float mx = fmaxf(p0, p1);
                #pragma unroll
                for (int off = 16; off; off >>= 1)
                    mx = fmaxf(mx, __shfl_xor_sync(0xffffffffu, mx, off));
                float e0 = expf(p0 - mx), e1 = expf(p1 - mx);
                float z = e0 + e1;
                #pragma unroll
                for (int off = 16; off; off >>= 1)
                    z += __shfl_xor_sync(0xffffffffu, z, off);
                float av0 = e0 / z, av1 = e1 / z;
                float bv; int bi;
                if (av0 >= av1) { bv = av0; bi = 2 * lane; } else { bv = av1; bi = 2 * lane + 1; }
                #pragma unroll
                for (int off = 16; off; off >>= 1) {
                    float ov = __shfl_xor_sync(0xffffffffu, bv, off);
                    int   oi = __shfl_xor_sync(0xffffffffu, bi, off);
                    if (ov > bv || (ov == bv && oi < bi)) { bv = ov; bi = oi; }
                }
                if (lane == 0) {
                    int pos = (i + node) - s0;
                    argout[(size_t)g * MAXN + pos] = (float)bi;
                }
            }
        }

        // sumA accumulation (threads < 64)
        if (t < NC) {
            float sa = sAcc[t];
            int gidx = t >> 1, par = t & 1;
            for (int n = 0; n < nb; n++)
                sa += As[n * NC + 2 * (gidx ^ (n & 31)) + par];
            sAcc[t] = sa;
        }

        // ---- convert A -> AbfH/AbfL ([c][n], rows 128B SW128) ----
        {
            int c = t >> 3, n0 = (t & 7) * 8;
            u32 ph[4], pl[4];
            #pragma unroll
            for (int q = 0; q < 4; q++) {
                int na = n0 + 2 * q, nb2 = na + 1;
                float va = (na < nb)  ? As[na * NC + 2 * ((c >> 1) ^ (na & 31)) + (c & 1)] : 0.f;
                float vb = (nb2 < nb) ? As[nb2 * NC + 2 * ((c >> 1) ^ (nb2 & 31)) + (c & 1)] : 0.f;
                split2(va, vb, ph[q], pl[q]);
            }
            u32 so = (c * 128 + n0 * 2);
            so = so ^ ((so >> 3) & 0x70);
            *(uint4*)((char*)smem + (abH - sb) + so) = make_uint4(ph[0], ph[1], ph[2], ph[3]);
            *(uint4*)((char*)smem + (abL - sb) + so) = make_uint4(pl[0], pl[1], pl[2], pl[3]);
        }
        __syncthreads();

        // ---- Phase D (tensor): acc += A[c][n] * X[n][d] ----
        #pragma unroll
        for (int ks = 0; ks < 4; ks++) {
            u32 a_off = (a_row << 7) + (((2 * ks + a_hi) ^ a_sw) << 4);
            u32 ah0, ah1, ah2, ah3, al0, al1, al2, al3;
            LDSM4(ah0, ah1, ah2, ah3, abH + a_off);
            LDSM4(al0, al1, al2, al3, abL + a_off);
            int k_row = 16 * ks + pd_ksub;
            u32 bbase = k_row * 512;
            u32 bsw = (k_row & 7) << 4;
            #pragma unroll
            for (int jj = 0; jj < 4; jj++) {
                u32 b_off = bbase + ((128 * wc + 32 * jj + 16 * pd_dh) ^ bsw);
                u32 bh0, bh1, bh2, bh3, bl0, bl1, bl2, bl3;
                LDSM4T(bh0, bh1, bh2, bh3, xnH + b_off);
                LDSM4T(bl0, bl1, bl2, bl3, xnL + b_off);
                MMA16816(acc[2 * jj],     ah0, ah1, ah2, ah3, bh0, bh1);
                MMA16816(acc[2 * jj + 1], ah0, ah1, ah2, ah3, bh2, bh3);
                MMA16816(acc[2 * jj],     al0, al1, al2, al3, bh0, bh1);
                MMA16816(acc[2 * jj + 1], al0, al1, al2, al3, bh2, bh3);
                MMA16816(acc[2 * jj],     ah0, ah1, ah2, ah3, bl0, bl1);
                MMA16816(acc[2 * jj + 1], ah0, ah1, ah2, ah3, bl2, bl3);
            }
        }
        __syncthreads();
    }

    // ---- flush accumulators ----
    {
        float* pgb = g_P + (size_t)g * NC * D;
        int r0 = 16 * wr + (lane >> 2);
        #pragma unroll
        for (int nj = 0; nj < 8; nj++) {
            int col = 64 * wc + 8 * nj + 2 * (lane & 3);
            atomicAdd(pgb + (size_t)r0 * D + col,           acc[nj][0]);
            atomicAdd(pgb + (size_t)r0 * D + col + 1,       acc[nj][1]);
            atomicAdd(pgb + (size_t)(r0 + 8) * D + col,     acc[nj][2]);
            atomicAdd(pgb + (size_t)(r0 + 8) * D + col + 1, acc[nj][3]);
        }
    }
    if (t < NC) atomicAdd(&g_sumA[g * NC + t], sAcc[t]);
}

// ---------------- epilogue GEMMs: register-tiled f32x2 ----------------
#define ASTR 34
template <int MODE>
__global__ __launch_bounds__(256) void k_gemm(const float* __restrict__ Bmat,
                                              const float* __restrict__ bias,
                                              float* __restrict__ Cout) {
    __shared__ float Ash[D * ASTR];
    int t = threadIdx.x;
    int tx = t & 127, ty = t >> 7;
    int r0 = blockIdx.x * 32;
    const float* Amat = (MODE == 0) ? g_P : g_H;

    {   // stage A [32r][256k] -> Ash[k][r]
        int row = t >> 3, k4 = (t & 7) * 4;
        const float* src = Amat + (size_t)(r0 + row) * D + k4;
        #pragma unroll
        for (int it = 0; it < 8; it++) {
            float4 v = *(const float4*)(src + 32 * it);
            int kb = k4 + 32 * it;
            Ash[(kb + 0) * ASTR + row] = v.x;
            Ash[(kb + 1) * ASTR + row] = v.y;
            Ash[(kb + 2) * ASTR + row] = v.z;
            Ash[(kb + 3) * ASTR + row] = v.w;
        }
    }
    __syncthreads();

    int q0 = 2 * tx;
    int rbase = 16 * ty;
    ull acc2[8][2];
    #pragma unroll
    for (int p = 0; p < 8; p++) { acc2[p][0] = 0ull; acc2[p][1] = 0ull; }

    const float* b0p = Bmat + (size_t)q0 * D;
    const float* b1p = Bmat + (size_t)(q0 + 1) * D;
    for (int k = 0; k < D; k += 4) {
        float4 bv0 = *(const float4*)(b0p + k);
        float4 bv1 = *(const float4*)(b1p + k);
        float b0s[4] = {bv0.x, bv0.y, bv0.z, bv0.w};
        float b1s[4] = {bv1.x, bv1.y, bv1.z, bv1.w};
        #pragma unroll
        for (int kk = 0; kk < 4; kk++) {
            ull bd0, bd1;
            DUP(bd0, b0s[kk]);
            DUP(bd1, b1s[kk]);
            const ull* ar = (const ull*)(Ash + (k + kk) * ASTR + rbase);
            #pragma unroll
            for (int p = 0; p < 8; p++) {
                ull av = ar[p];
                FMA2(acc2[p][0], av, bd0);
                FMA2(acc2[p][1], av, bd1);
            }
        }
    }

    float bias0 = bias[q0], bias1 = bias[q0 + 1];
    #pragma unroll
    for (int p = 0; p < 8; p++) {
        int r = r0 + rbase + 2 * p;
        float v00 = __uint_as_float((u32)(acc2[p][0] & 0xffffffffull));
        float v01 = __uint_as_float((u32)(acc2[p][1] & 0xffffffffull));
        float v10 = __uint_as_float((u32)(acc2[p][0] >> 32));
        float v11 = __uint_as_float((u32)(acc2[p][1] >> 32));
        if (MODE == 0) {
            int c0 = r & (NC - 1), c1 = (r + 1) & (NC - 1);
            float sa0 = g_sumA[r], sa1 = g_sumA[r + 1];
            v00 += g_Q[c0 * D + q0]     + sa0 * bias0;
            v01 += g_Q[c0 * D + q0 + 1] + sa0 * bias1;
            v10 += g_Q[c1 * D + q0]     + sa1 * bias0;
            v11 += g_Q[c1 * D + q0 + 1] + sa1 * bias1;
            *(float2*)(g_H + (size_t)r * D + q0)       = make_float2(v00, v01);
            *(float2*)(g_H + (size_t)(r + 1) * D + q0) = make_float2(v10, v11);
        } else {
            v00 = fmaxf(v00 + bias0, 0.f);
            v01 = fmaxf(v01 + bias1, 0.f);
            v10 = fmaxf(v10 + bias0, 0.f);
            v11 = fmaxf(v11 + bias1, 0.f);
            *(float2*)(Cout + (size_t)r * D + q0)       = make_float2(v00, v01);
            *(float2*)(Cout + (size_t)(r + 1) * D + q0) = make_float2(v10, v11);
        }
    }
}

// ---------------- mask output ----------------
__global__ void k_mask(float* __restrict__ maskout) {
    int idx = blockIdx.x * blockDim.x + threadIdx.x;
    if (idx >= NB * MAXN) return;
    int b = idx >> 12, pos = idx & (MAXN - 1);
    int cnt = g_starts[b + 1] - g_starts[b];
    maskout[idx] = (pos < cnt) ? 1.f : 0.f;
}

extern "C" void kernel_launch(void* const* d_in, const int* in_sizes, int n_in,
                              void* d_out, int out_size) {
    const float* x    = (const float*)d_in[0];
    const void*  bat  = d_in[1];
    const float* Qp   = (const float*)d_in[2];
    const float* WQ_w = (const float*)d_in[3];
    const float* WQ_b = (const float*)d_in[4];
    const float* WK_w = (const float*)d_in[5];
    const float* WK_b = (const float*)d_in[6];
    const float* WV_w = (const float*)d_in[7];
    const float* WV_b = (const float*)d_in[8];
    const float* WO_w = (const float*)d_in[9];
    const float* WO_b = (const float*)d_in[10];
    (void)n_in;

    int n_nodes = in_sizes[0] / D;
    float* out = (float*)d_out;
    int has_arg  = out_size >= (NB * NC * D + NB * MAXN);
    int has_mask = out_size >= (NB * NC * D + 2 * NB * MAXN);
    float* argout  = out + NB * NC * D;
    float* maskout = argout + NB * MAXN;

    void *pP = nullptr, *pS = nullptr;
    cudaGetSymbolAddress(&pP, g_P);
    cudaGetSymbolAddress(&pS, g_sumA);
    cudaMemsetAsync(pP, 0, sizeof(float) * NB * NC * D, 0);
    cudaMemsetAsync(pS, 0, sizeof(float) * NB * NC, 0);
    if (has_arg) cudaMemsetAsync(argout, 0, sizeof(float) * NB * MAXN, 0);

    k_meta<<<1, NB>>>(bat, n_nodes);
    k_q<<<NC, 256>>>(Qp, WQ_w, WQ_b);
    k_qt<<<NC, 256>>>(WK_w, WK_b);

    const int smem_main = SMEM_FLOATS * (int)sizeof(float);
    cudaFuncSetAttribute(k_main, cudaFuncAttributeMaxDynamicSharedMemorySize, smem_main);
    k_main<<<NB * SPG, NT, smem_main>>>(x, argout, has_arg);

    k_gemm<0><<<(NB * NC) / 32, 256>>>(WV_w, WV_b, nullptr);
    k_gemm<1><<<(NB * NC) / 32, 256>>>(WO_w, WO_b, out);

    if (has_mask) k_mask<<<(NB * MAXN) / 256, 256>>>(maskout);
}

// round 13
// speedup vs baseline: 1.0652x; 1.0030x over previous
#include <cuda_runtime.h>
#include <cuda_bf16.h>

#define D 256
#define NC 64
#define NB 64
#define MAXN 4096
#define SPG 16
#define TILE 64
#define NT 512
#define FLAG_EPS 3e-6f

typedef unsigned long long ull;
typedef unsigned int u32;

#define FMA2(acc, a, b) asm("fma.rn.f32x2 %0, %1, %2, %0;" : "+l"(acc) : "l"(a), "l"(b))
#define DUP(d, x)       asm("mov.b64 %0, {%1, %1};" : "=l"(d) : "r"(__float_as_uint(x)))
#define CVTBF2(r, lo, hi) asm("cvt.rn.bf16x2.f32 %0, %1, %2;" : "=r"(r) : "f"(hi), "f"(lo))

#define CP16(dst, src) \
    asm volatile("cp.async.cg.shared.global [%0], [%1], 16;" :: "r"(dst), "l"(src))
#define CPCOMMIT() asm volatile("cp.async.commit_group;" ::: "memory")
#define CPWAIT0()  asm volatile("cp.async.wait_group 0;" ::: "memory")

#define LDSM4(r0, r1, r2, r3, addr) \
    asm volatile("ldmatrix.sync.aligned.m8n8.x4.shared.b16 {%0,%1,%2,%3}, [%4];" \
                 : "=r"(r0), "=r"(r1), "=r"(r2), "=r"(r3) : "r"(addr))

#define LDSM4T(r0, r1, r2, r3, addr) \
    asm volatile("ldmatrix.sync.aligned.m8n8.x4.trans.shared.b16 {%0,%1,%2,%3}, [%4];" \
                 : "=r"(r0), "=r"(r1), "=r"(r2), "=r"(r3) : "r"(addr))

#define MMA16816(c, a0, a1, a2, a3, b0, b1) \
    asm volatile("mma.sync.aligned.m16n8k16.row.col.f32.bf16.bf16.f32 " \
                 "{%0,%1,%2,%3}, {%4,%5,%6,%7}, {%8,%9}, {%0,%1,%2,%3};" \
                 : "+f"((c)[0]), "+f"((c)[1]), "+f"((c)[2]), "+f"((c)[3]) \
                 : "r"(a0), "r"(a1), "r"(a2), "r"(a3), "r"(b0), "r"(b1))

__device__ int   g_starts[NB + 1];
__device__ float g_Q[NC * D];
__device__ float g_QtT[D * NC];   // [e][c] (fallback)
__device__ float g_QtC[NC * D];   // [c][e] (bf16 conversion source)
__device__ float g_cK[NC];
__device__ float g_P[NB * NC * D];
__device__ float g_sumA[NB * NC];
__device__ float g_H[NB * NC * D];

__device__ __forceinline__ u32 s2u(const void* p) {
    u32 a;
    asm("{ .reg .u64 t; cvta.to.shared.u64 t, %1; cvt.u32.u64 %0, t; }" : "=r"(a) : "l"(p));
    return a;
}

__device__ __forceinline__ void split2(float v0, float v1, u32& hi, u32& lo) {
    CVTBF2(hi, v0, v1);
    float h0 = __uint_as_float(hi << 16);
    float h1 = __uint_as_float(hi & 0xffff0000u);
    CVTBF2(lo, v0 - h0, v1 - h1);
}

// ---------------- meta ----------------
__global__ void k_meta(const void* __restrict__ batch, int n) {
    __shared__ int sh_is32;
    int t = threadIdx.x;
    if (t == 0) {
        long long v = ((const long long*)batch)[n / 4];
        sh_is32 = (v < 0 || v >= NB) ? 1 : 0;
    }
    __syncthreads();
    int is32 = sh_is32;
    int lo = 0, hi = n;
    while (lo < hi) {
        int mid = (lo + hi) >> 1;
        long long bv = is32 ? (long long)((const int*)batch)[mid]
                            : ((const long long*)batch)[mid];
        if (bv < (long long)t) lo = mid + 1; else hi = mid;
    }
    g_starts[t] = lo;
    if (t == 0) g_starts[NB] = n;
}

// ---------------- Q = Qp @ WQ^T + bQ ----------------
__global__ void k_q(const float* __restrict__ Qp, const float* __restrict__ Wq,
                    const float* __restrict__ bq) {
    int c = blockIdx.x, d = threadIdx.x;
    __shared__ float qp[D];
    qp[d] = Qp[c * D + d];
    __syncthreads();
    float a0 = 0.f, a1 = 0.f, a2 = 0.f, a3 = 0.f;
    #pragma unroll 4
    for (int e = 0; e < D; e += 4) {
        a0 = fmaf(qp[e + 0], Wq[d * D + e + 0], a0);
        a1 = fmaf(qp[e + 1], Wq[d * D + e + 1], a1);
        a2 = fmaf(qp[e + 2], Wq[d * D + e + 2], a2);
        a3 = fmaf(qp[e + 3], Wq[d * D + e + 3], a3);
    }
    g_Q[c * D + d] = ((a0 + a1) + (a2 + a3)) + bq[d];
}

// ---------------- Qt[c][e]; cK[c] ----------------
__global__ void k_qt(const float* __restrict__ Wk, const float* __restrict__ bk) {
    int c = blockIdx.x, e = threadIdx.x;
    __shared__ float q[D];
    q[e] = g_Q[c * D + e];
    __syncthreads();
    float a0 = 0.f, a1 = 0.f;
    #pragma unroll 4
    for (int d = 0; d < D; d += 2) {
        a0 = fmaf(q[d + 0], Wk[(d + 0) * D + e], a0);
        a1 = fmaf(q[d + 1], Wk[(d + 1) * D + e], a1);
    }
    float v = a0 + a1;
    g_QtT[e * NC + c] = v;
    g_QtC[c * D + e] = v;
    if (e == 0) {
        float ck = 0.f;
        for (int d = 0; d < D; d++) ck += q[d] * bk[d];
        g_cK[c] = ck;
    }
}

// ---------------- main fused kernel ----------------
// smem floats:
//   XnbfH [0,8192)      bf16-hi x [64n][256e], rows 512B, swz off^((n&7)<<4)
//   XnbfL [8192,16384)
//   QtbfH [16384,24576) bf16-hi Qt [64c][256e], rows 512B
//   QtbfL [24576,32768)
//   As    [32768,36864) f32 pair-swizzled [n][c]: n*64 + 2*((c>>1)^(n&31)) + (c&1)
//   AbfH  [36864,38912) bf16-hi A [64c][64n], rows 128B, SW128
//   AbfL  [38912,40960)
//   cKs 40960, sAcc 41024, flags 41088
//   raw   [41216, 57600) f32 staging [64n][256e] linear (cp.async target)
#define SMEM_FLOATS 57600
extern __shared__ float smem[];

__global__ __launch_bounds__(NT, 1) void k_main(const float* __restrict__ x,
                                                float* __restrict__ argout, int has_arg) {
    float* As   = smem + 32768;
    float* cKs  = smem + 40960;
    float* sAcc = smem + 41024;
    int*   flagn = (int*)(smem + 41088);
    int*   flagl = (int*)(smem + 41089);
    float* rawF = smem + 41216;

    int t = threadIdx.x;
    int g = blockIdx.x / SPG, sl = blockIdx.x % SPG;
    int s0 = g_starts[g], s1 = g_starts[g + 1];
    int cnt = s1 - s0;
    int chunk = (cnt + SPG - 1) / SPG;
    int i0 = s0 + sl * chunk;
    int i1 = min(i0 + chunk, s1);
    if (i0 >= i1) return;  // uniform across block

    u32 sb = s2u(smem);
    const u32 xnH = sb, xnL = sb + 32768;
    const u32 qtH = sb + 65536, qtL = sb + 98304;
    const u32 abH = sb + 147456, abL = sb + 155648;
    const u32 rawU = sb + 41216u * 4u;

    // prologue: prefetch first tile into raw staging
    {
        int nbj = min(TILE, i1 - i0);
        for (int r = t; r < nbj * 64; r += NT) {
            int n = r >> 6, e4 = r & 63;
            CP16(rawU + (u32)r * 16u, x + (size_t)(i0 + n) * D + 4 * e4);
        }
        CPCOMMIT();
    }

    // init: zero Xnbf, load cK, convert Qt -> split bf16 [c][e]
    for (int r = t; r < 16384; r += NT) ((u32*)smem)[r] = 0u;
    if (t < NC) { cKs[t] = g_cK[t]; sAcc[t] = 0.f; }
    if (t == 0) *flagn = 0;
    for (int r = t; r < NC * (D / 4); r += NT) {
        int c = r >> 6, e4 = r & 63;
        float4 v = *(const float4*)(g_QtC + c * D + 4 * e4);
        u32 h0, l0, h1, l1;
        split2(v.x, v.y, h0, l0);
        split2(v.z, v.w, h1, l1);
        u32 off = c * 512 + ((e4 * 8) ^ ((c & 7) << 4));
        *(uint2*)((char*)smem + (qtH - sb) + off) = make_uint2(h0, h1);
        *(uint2*)((char*)smem + (qtL - sb) + off) = make_uint2(l0, l1);
    }

    const int lane = t & 31;
    const int w    = t >> 5;            // 0..15

    // Phase-B MMA mapping: cw = c-block(16), nw = n-block(16)
    const int cw = w & 3, nw = w >> 2;
    const int pb_arow = 16 * cw + (lane & 7) + 8 * ((lane >> 3) & 1);
    const int pb_ae   = (lane >> 4) & 1;
    const int pb_asw  = (pb_arow & 7) << 4;
    const int pb_brow = 16 * nw + (lane & 7) + 8 * ((lane >> 4) & 1);
    const int pb_be   = (lane >> 3) & 1;
    const int pb_bsw  = (pb_brow & 7) << 4;
    const int wo_c = 16 * cw + (lane >> 2);
    const int wo_n = 16 * nw + 2 * (lane & 3);

    // Phase-D mapping: wr = c-block(16), wc = d-block(64)
    const int wr = w & 3, wc = w >> 2;
    const int a_row = 16 * wr + (lane & 7) + 8 * ((lane >> 3) & 1);
    const int a_hi = lane >> 4;
    const int a_sw = a_row & 7;
    const int pd_ksub = (lane & 7) + 8 * ((lane >> 3) & 1);
    const int pd_dh = (lane >> 4) & 1;

    // sumA mapping: warps 0..7, 4 lanes per cluster, 16 nodes per lane
    const int sa_c = (w < 8) ? (8 * w + (lane >> 2)) : 0;
    const int sa_q = lane & 3;

    float acc[8][4];
    #pragma unroll
    for (int nj = 0; nj < 8; nj++)
        #pragma unroll
        for (int q = 0; q < 4; q++) acc[nj][q] = 0.f;

    __syncthreads();

    for (int i = i0; i < i1; i += TILE) {
        int nb = min(TILE, i1 - i);

        // ---- wait prefetch, convert raw -> split bf16 Xnbf [n][e] ----
        CPWAIT0();
        __syncthreads();
        if (t == 0) *flagn = 0;
        for (int r = t; r < nb * 64; r += NT) {
            int n = r >> 6, e4 = r & 63;
            float4 v = *(const float4*)(rawF + (size_t)r * 4);
            u32 h0, l0, h1, l1;
            split2(v.x, v.y, h0, l0);
            split2(v.z, v.w, h1, l1);
            u32 off = n * 512 + ((e4 * 8) ^ ((n & 7) << 4));
            *(uint2*)((char*)smem + off)         = make_uint2(h0, h1);
            *(uint2*)((char*)smem + 32768 + off) = make_uint2(l0, l1);
        }
        __syncthreads();   // Xn ready AND raw fully consumed

        // ---- prefetch next tile into raw (overlaps B/C/D) ----
        if (i + TILE < i1) {
            int j = i + TILE;
            int nbj = min(TILE, i1 - j);
            for (int r = t; r < nbj * 64; r += NT) {
                int n = r >> 6, e4 = r & 63;
                CP16(rawU + (u32)r * 16u, x + (size_t)(j + n) * D + 4 * e4);
            }
            CPCOMMIT();
        }

        // ---- Phase B (tensor): S[16c x 16n] per warp, k = 256 ----
        {
            float sc[4][4];
            #pragma unroll
            for (int p = 0; p < 4; p++)
                #pragma unroll
                for (int q = 0; q < 4; q++) sc[p][q] = 0.f;
            #pragma unroll
            for (int ks = 0; ks < 16; ks++) {
                const int pe = (ks & 1) * 2;
                u32 aoff = pb_arow * 512 + ((32 * ks + 16 * pb_ae) ^ pb_asw);
                u32 boff = pb_brow * 512 + ((32 * ks + 16 * pb_be) ^ pb_bsw);
                u32 ah0, ah1, ah2, ah3, al0, al1, al2, al3;
                u32 bh0, bh1, bh2, bh3, bl0, bl1, bl2, bl3;
                LDSM4(ah0, ah1, ah2, ah3, qtH + aoff);
                LDSM4(al0, al1, al2, al3, qtL + aoff);
                LDSM4(bh0, bh1, bh2, bh3, xnH + boff);
                LDSM4(bl0, bl1, bl2, bl3, xnL + boff);
                MMA16816(sc[pe],     ah0, ah1, ah2, ah3, bh0, bh1);
                MMA16816(sc[pe + 1], ah0, ah1, ah2, ah3, bh2, bh3);
                MMA16816(sc[pe],     al0, al1, al2, al3, bh0, bh1);
                MMA16816(sc[pe + 1], al0, al1, al2, al3, bh2, bh3);
                MMA16816(sc[pe],     ah0, ah1, ah2, ah3, bl0, bl1);
                MMA16816(sc[pe + 1], ah0, ah1, ah2, ah3, bl2, bl3);
            }
            float ck0 = cKs[wo_c], ck1 = cKs[wo_c + 8];
            #pragma unroll
            for (int h = 0; h < 2; h++) {
                float v0 = sc[h][0] + sc[h + 2][0];
                float v1 = sc[h][1] + sc[h + 2][1];
                float v2 = sc[h][2] + sc[h + 2][2];
                float v3 = sc[h][3] + sc[h + 2][3];
                int n0 = wo_n + 8 * h;
                int m0 = n0 & 31, m1 = (n0 + 1) & 31;
                As[n0 * 64 + 2 * ((wo_c >> 1) ^ m0) + (wo_c & 1)] = v0 + ck0;
                As[(n0 + 1) * 64 + 2 * ((wo_c >> 1) ^ m1) + (wo_c & 1)] = v1 + ck0;
                int c1 = wo_c + 8;
                As[n0 * 64 + 2 * ((c1 >> 1) ^ m0) + (c1 & 1)] = v2 + ck1;
                As[(n0 + 1) * 64 + 2 * ((c1 >> 1) ^ m1) + (c1 & 1)] = v3 + ck1;
            }
        }
        __syncthreads();

        // ---- Phase C: softmax + argmax, 2 nodes per warp interleaved ----
        #pragma unroll
        for (int r = 0; r < 2; r++) {
            int nA = 32 * r + w, nB = nA + 16;
            if (nA >= nb) break;                     // warp-uniform
            bool aB = nB < nb;                       // warp-uniform
            int mA_ = nA & 31, mB_ = nB & 31;
            int offA0 = nA * NC + 2 * ((lane >> 1) ^ mA_) + (lane & 1);
            int offA1 = nA * NC + 2 * (((lane >> 1) + 16) ^ mA_) + (lane & 1);
            int offB0 = nB * NC + 2 * ((lane >> 1) ^ mB_) + (lane & 1);
            int offB1 = nB * NC + 2 * (((lane >> 1) + 16) ^ mB_) + (lane & 1);
            float pA0 = As[offA0] * 0.0625f, pA1 = As[offA1] * 0.0625f;
            float pB0 = aB ? As[offB0] * 0.0625f : 0.f;
            float pB1 = aB ? As[offB1] * 0.0625f : 0.f;
            float mxA = fmaxf(pA0, pA1), mxB = fmaxf(pB0, pB1);
            #pragma unroll
            for (int off = 16; off; off >>= 1) {
                mxA = fmaxf(mxA, __shfl_xor_sync(0xffffffffu, mxA, off));
                mxB = fmaxf(mxB, __shfl_xor_sync(0xffffffffu, mxB, off));
            }
            float eA0 = __expf(pA0 - mxA), eA1 = __expf(pA1 - mxA);
            float eB0 = __expf(pB0 - mxB), eB1 = __expf(pB1 - mxB);
            float zA = eA0 + eA1, zB = eB0 + eB1;
            #pragma unroll
            for (int off = 16; off; off >>= 1) {
                zA += __shfl_xor_sync(0xffffffffu, zA, off);
                zB += __shfl_xor_sync(0xffffffffu, zB, off);
            }
            float rzA = __fdividef(1.f, zA), rzB = __fdividef(1.f, zB);
            float avA0 = eA0 * rzA, avA1 = eA1 * rzA;
            float avB0 = eB0 * rzB, avB1 = eB1 * rzB;
            float bvA; int biA;
            if (avA0 >= avA1) { bvA = avA0; biA = lane; } else { bvA = avA1; biA = lane + 32; }
            float bvB; int biB;
            if (avB0 >= avB1) { bvB = avB0; biB = lane; } else { bvB = avB1; biB = lane + 32; }
            #pragma unroll
            for (int off = 16; off; off >>= 1) {
                float ovA = __shfl_xor_sync(0xffffffffu, bvA, off);
                int   oiA = __shfl_xor_sync(0xffffffffu, biA, off);
                float ovB = __shfl_xor_sync(0xffffffffu, bvB, off);
                int   oiB = __shfl_xor_sync(0xffffffffu, biB, off);
                if (ovA > bvA || (ovA == bvA && oiA < biA)) { bvA = ovA; biA = oiA; }
                if (ovB > bvB || (ovB == bvB && oiB < biB)) { bvB = ovB; biB = oiB; }
            }
            As[offA0] = avA0;
            As[offA1] = avA1;
            if (aB) { As[offB0] = avB0; As[offB1] = avB1; }
            // second best (excluding winner), interleaved
            float xA0 = (biA == lane) ? -1e30f : avA0;
            float xA1 = (biA == lane + 32) ? -1e30f : avA1;
            float xB0 = (biB == lane) ? -1e30f : avB0;
            float xB1 = (biB == lane + 32) ? -1e30f : avB1;
            float m2A = fmaxf(xA0, xA1), m2B = fmaxf(xB0, xB1);
            #pragma unroll
            for (int off = 16; off; off >>= 1) {
                m2A = fmaxf(m2A, __shfl_xor_sync(0xffffffffu, m2A, off));
                m2B = fmaxf(m2B, __shfl_xor_sync(0xffffffffu, m2B, off));
            }
            if (lane == 0) {
                if (has_arg) {
                    int posA = (i + nA) - s0;
                    argout[(size_t)g * MAXN + posA] = (float)biA;
                    if (aB) {
                        int posB = (i + nB) - s0;
                        argout[(size_t)g * MAXN + posB] = (float)biB;
                    }
                }
                if (bvA - m2A < FLAG_EPS) { int k = atomicAdd(flagn, 1); flagl[k] = nA; }
                if (aB && (bvB - m2B < FLAG_EPS)) { int k = atomicAdd(flagn, 1); flagl[k] = nB; }
            }
        }
        __syncthreads();

        // ---- fallback: exact argmax for flagged nodes (rare; reference-exact path) ----
        int nf = *flagn;
        if (has_arg) {
            for (int f = w; f < nf; f += 16) {
                int node = flagl[f];
                const float* xr = x + (size_t)(i + node) * D;
                float fs0 = 0.f, fs1 = 0.f;
                for (int e = 0; e < D; e++) {
                    float xe = __ldg(xr + e);
                    float2 q = *(const float2*)(g_QtT + e * NC + 2 * lane);
                    fs0 = fmaf(xe, q.x, fs0);
                    fs1 = fmaf(xe, q.y, fs1);
                }
                fs0 += cKs[2 * lane];
                fs1 += cKs[2 * lane + 1];
                float p0 = fs0 * 0.0625f, p1 = fs1 * 0.0625f;
                float mx = fmaxf(p0, p1);
                #pragma unroll
                for (int off = 16; off; off >>= 1)
                    mx = fmaxf(mx, __shfl_xor_sync(0xffffffffu, mx, off));
                float e0 = expf(p0 - mx), e1 = expf(p1 - mx);
                float z = e0 + e1;
                #pragma unroll
                for (int off = 16; off; off >>= 1)
                    z += __shfl_xor_sync(0xffffffffu, z, off);
                float av0 = e0 / z, av1 = e1 / z;
                float bv; int bi;
                if (av0 >= av1) { bv = av0; bi = 2 * lane; } else { bv = av1; bi = 2 * lane + 1; }
                #pragma unroll
                for (int off = 16; off; off >>= 1) {
                    float ov = __shfl_xor_sync(0xffffffffu, bv, off);
                    int   oi = __shfl_xor_sync(0xffffffffu, bi, off);
                    if (ov > bv || (ov == bv && oi < bi)) { bv = ov; bi = oi; }
                }
                if (lane == 0) {
                    int pos = (i + node) - s0;
                    argout[(size_t)g * MAXN + pos] = (float)bi;
                }
            }
        }

        // ---- sumA: warps 0..7, 4 lanes per cluster x 16 nodes each ----
        if (w < 8) {
            int c = sa_c;
            int gidx = c >> 1, par = c & 1;
            float sa = 0.f;
            int nlo = sa_q * 16, nhi = min(nlo + 16, nb);
            for (int n = nlo; n < nhi; n++)
                sa += As[n * NC + 2 * (gidx ^ (n & 31)) + par];
            sa += __shfl_xor_sync(0xffffffffu, sa, 1);
            sa += __shfl_xor_sync(0xffffffffu, sa, 2);
            if (sa_q == 0) sAcc[c] += sa;
        }

        // ---- convert A -> AbfH/AbfL ([c][n], rows 128B SW128) ----
        {
            int c = t >> 3, n0 = (t & 7) * 8;
            u32 ph[4], pl[4];
            #pragma unroll
            for (int q = 0; q < 4; q++) {
                int na = n0 + 2 * q, nb2 = na + 1;
                float va = (na < nb)  ? As[na * NC + 2 * ((c >> 1) ^ (na & 31)) + (c & 1)] : 0.f;
                float vb = (nb2 < nb) ? As[nb2 * NC + 2 * ((c >> 1) ^ (nb2 & 31)) + (c & 1)] : 0.f;
                split2(va, vb, ph[q], pl[q]);
            }
            u32 so = (c * 128 + n0 * 2);
            so = so ^ ((so >> 3) & 0x70);
            *(uint4*)((char*)smem + (abH - sb) + so) = make_uint4(ph[0], ph[1], ph[2], ph[3]);
            *(uint4*)((char*)smem + (abL - sb) + so) = make_uint4(pl[0], pl[1], pl[2], pl[3]);
        }
        __syncthreads();

        // ---- Phase D (tensor): acc += A[c][n] * X[n][d] ----
        #pragma unroll
        for (int ks = 0; ks < 4; ks++) {
            u32 a_off = (a_row << 7) + (((2 * ks + a_hi) ^ a_sw) << 4);
            u32 ah0, ah1, ah2, ah3, al0, al1, al2, al3;
            LDSM4(ah0, ah1, ah2, ah3, abH + a_off);
            LDSM4(al0, al1, al2, al3, abL + a_off);
            int k_row = 16 * ks + pd_ksub;
            u32 bbase = k_row * 512;
            u32 bsw = (k_row & 7) << 4;
            #pragma unroll
            for (int jj = 0; jj < 4; jj++) {
                u32 b_off = bbase + ((128 * wc + 32 * jj + 16 * pd_dh) ^ bsw);
                u32 bh0, bh1, bh2, bh3, bl0, bl1, bl2, bl3;
                LDSM4T(bh0, bh1, bh2, bh3, xnH + b_off);
                LDSM4T(bl0, bl1, bl2, bl3, xnL + b_off);
                MMA16816(acc[2 * jj],     ah0, ah1, ah2, ah3, bh0, bh1);
                MMA16816(acc[2 * jj + 1], ah0, ah1, ah2, ah3, bh2, bh3);
                MMA16816(acc[2 * jj],     al0, al1, al2, al3, bh0, bh1);
                MMA16816(acc[2 * jj + 1], al0, al1, al2, al3, bh2, bh3);
                MMA16816(acc[2 * jj],     ah0, ah1, ah2, ah3, bl0, bl1);
                MMA16816(acc[2 * jj + 1], ah0, ah1, ah2, ah3, bl2, bl3);
            }
        }
        __syncthreads();
    }

    // ---- flush accumulators ----
    {
        float* pgb = g_P + (size_t)g * NC * D;
        int r0 = 16 * wr + (lane >> 2);
        #pragma unroll
        for (int nj = 0; nj < 8; nj++) {
            int col = 64 * wc + 8 * nj + 2 * (lane & 3);
            atomicAdd(pgb + (size_t)r0 * D + col,           acc[nj][0]);
            atomicAdd(pgb + (size_t)r0 * D + col + 1,       acc[nj][1]);
            atomicAdd(pgb + (size_t)(r0 + 8) * D + col,     acc[nj][2]);
            atomicAdd(pgb + (size_t)(r0 + 8) * D + col + 1, acc[nj][3]);
        }
    }
    if (t < NC) atomicAdd(&g_sumA[g * NC + t], sAcc[t]);
}

// ---------------- epilogue GEMMs: register-tiled f32x2 ----------------
#define ASTR 34
template <int MODE>
__global__ __launch_bounds__(256) void k_gemm(const float* __restrict__ Bmat,
                                              const float* __restrict__ bias,
                                              float* __restrict__ Cout) {
    __shared__ float Ash[D * ASTR];
    int t = threadIdx.x;
    int tx = t & 127, ty = t >> 7;
    int r0 = blockIdx.x * 32;
    const float* Amat = (MODE == 0) ? g_P : g_H;

    {   // stage A [32r][256k] -> Ash[k][r]
        int row = t >> 3, k4 = (t & 7) * 4;
        const float* src = Amat + (size_t)(r0 + row) * D + k4;
        #pragma unroll
        for (int it = 0; it < 8; it++) {
            float4 v = *(const float4*)(src + 32 * it);
            int kb = k4 + 32 * it;
            Ash[(kb + 0) * ASTR + row] = v.x;
            Ash[(kb + 1) * ASTR + row] = v.y;
            Ash[(kb + 2) * ASTR + row] = v.z;
            Ash[(kb + 3) * ASTR + row] = v.w;
        }
    }
    __syncthreads();

    int q0 = 2 * tx;
    int rbase = 16 * ty;
    ull acc2[8][2];
    #pragma unroll
    for (int p = 0; p < 8; p++) { acc2[p][0] = 0ull; acc2[p][1] = 0ull; }

    const float* b0p = Bmat + (size_t)q0 * D;
    const float* b1p = Bmat + (size_t)(q0 + 1) * D;
    for (int k = 0; k < D; k += 4) {
        float4 bv0 = *(const float4*)(b0p + k);
        float4 bv1 = *(const float4*)(b1p + k);
        float b0s[4] = {bv0.x, bv0.y, bv0.z, bv0.w};
        float b1s[4] = {bv1.x, bv1.y, bv1.z, bv1.w};
        #pragma unroll
        for (int kk = 0; kk < 4; kk++) {
            ull bd0, bd1;
            DUP(bd0, b0s[kk]);
            DUP(bd1, b1s[kk]);
            const ull* ar = (const ull*)(Ash + (k + kk) * ASTR + rbase);
            #pragma unroll
            for (int p = 0; p < 8; p++) {
                ull av = ar[p];
                FMA2(acc2[p][0], av, bd0);
                FMA2(acc2[p][1], av, bd1);
            }
        }
    }

    float bias0 = bias[q0], bias1 = bias[q0 + 1];
    #pragma unroll
    for (int p = 0; p < 8; p++) {
        int r = r0 + rbase + 2 * p;
        float v00 = __uint_as_float((u32)(acc2[p][0] & 0xffffffffull));
        float v01 = __uint_as_float((u32)(acc2[p][1] & 0xffffffffull));
        float v10 = __uint_as_float((u32)(acc2[p][0] >> 32));
        float v11 = __uint_as_float((u32)(acc2[p][1] >> 32));
        if (MODE == 0) {
            int c0 = r & (NC - 1), c1 = (r + 1) & (NC - 1);
            float sa0 = g_sumA[r], sa1 = g_sumA[r + 1];
            v00 += g_Q[c0 * D + q0]     + sa0 * bias0;
            v01 += g_Q[c0 * D + q0 + 1] + sa0 * bias1;
            v10 += g_Q[c1 * D + q0]     + sa1 * bias0;
            v11 += g_Q[c1 * D + q0 + 1] + sa1 * bias1;
            *(float2*)(g_H + (size_t)r * D + q0)       = make_float2(v00, v01);
            *(float2*)(g_H + (size_t)(r + 1) * D + q0) = make_float2(v10, v11);
        } else {
            v00 = fmaxf(v00 + bias0, 0.f);
            v01 = fmaxf(v01 + bias1, 0.f);
            v10 = fmaxf(v10 + bias0, 0.f);
            v11 = fmaxf(v11 + bias1, 0.f);
            *(float2*)(Cout + (size_t)r * D + q0)       = make_float2(v00, v01);
            *(float2*)(Cout + (size_t)(r + 1) * D + q0) = make_float2(v10, v11);
        }
    }
}

// ---------------- mask output ----------------
__global__ void k_mask(float* __restrict__ maskout) {
    int idx = blockIdx.x * blockDim.x + threadIdx.x;
    if (idx >= NB * MAXN) return;
    int b = idx >> 12, pos = idx & (MAXN - 1);
    int cnt = g_starts[b + 1] - g_starts[b];
    maskout[idx] = (pos < cnt) ? 1.f : 0.f;
}

extern "C" void kernel_launch(void* const* d_in, const int* in_sizes, int n_in,
                              void* d_out, int out_size) {
    const float* x    = (const float*)d_in[0];
    const void*  bat  = d_in[1];
    const float* Qp   = (const float*)d_in[2];
    const float* WQ_w = (const float*)d_in[3];
    const float* WQ_b = (const float*)d_in[4];
    const float* WK_w = (const float*)d_in[5];
    const float* WK_b = (const float*)d_in[6];
    const float* WV_w = (const float*)d_in[7];
    const float* WV_b = (const float*)d_in[8];
    const float* WO_w = (const float*)d_in[9];
    const float* WO_b = (const float*)d_in[10];
    (void)n_in;

    int n_nodes = in_sizes[0] / D;
    float* out = (float*)d_out;
    int has_arg  = out_size >= (NB * NC * D + NB * MAXN);
    int has_mask = out_size >= (NB * NC * D + 2 * NB * MAXN);
    float* argout  = out + NB * NC * D;
    float* maskout = argout + NB * MAXN;

    void *pP = nullptr, *pS = nullptr;
    cudaGetSymbolAddress(&pP, g_P);
    cudaGetSymbolAddress(&pS, g_sumA);
    cudaMemsetAsync(pP, 0, sizeof(float) * NB * NC * D, 0);
    cudaMemsetAsync(pS, 0, sizeof(float) * NB * NC, 0);
    if (has_arg) cudaMemsetAsync(argout, 0, sizeof(float) * NB * MAXN, 0);

    k_meta<<<1, NB>>>(bat, n_nodes);
    k_q<<<NC, 256>>>(Qp, WQ_w, WQ_b);
    k_qt<<<NC, 256>>>(WK_w, WK_b);

    const int smem_main = SMEM_FLOATS * (int)sizeof(float);
    cudaFuncSetAttribute(k_main, cudaFuncAttributeMaxDynamicSharedMemorySize, smem_main);
    k_main<<<NB * SPG, NT, smem_main>>>(x, argout, has_arg);

    k_gemm<0><<<(NB * NC) / 32, 256>>>(WV_w, WV_b, nullptr);
    k_gemm<1><<<(NB * NC) / 32, 256>>>(WO_w, WO_b, out);

    if (has_mask) k_mask<<<(NB * MAXN) / 256, 256>>>(maskout);
}

// round 14
// speedup vs baseline: 1.1488x; 1.0784x over previous
#include <cuda_runtime.h>
#include <cuda_bf16.h>

#define D 256
#define NC 64
#define NB 64
#define MAXN 4096
#define SPG 16
#define TILE 64
#define NT 512
#define FLAG_EPS 3e-6f

typedef unsigned long long ull;
typedef unsigned int u32;

#define FMA2(acc, a, b) asm("fma.rn.f32x2 %0, %1, %2, %0;" : "+l"(acc) : "l"(a), "l"(b))
#define DUP(d, x)       asm("mov.b64 %0, {%1, %1};" : "=l"(d) : "r"(__float_as_uint(x)))
#define CVTBF2(r, lo, hi) asm("cvt.rn.bf16x2.f32 %0, %1, %2;" : "=r"(r) : "f"(hi), "f"(lo))

#define CP16(dst, src) \
    asm volatile("cp.async.cg.shared.global [%0], [%1], 16;" :: "r"(dst), "l"(src))
#define CPCOMMIT() asm volatile("cp.async.commit_group;" ::: "memory")
#define CPWAIT0()  asm volatile("cp.async.wait_group 0;" ::: "memory")

#define LDSM4(r0, r1, r2, r3, addr) \
    asm volatile("ldmatrix.sync.aligned.m8n8.x4.shared.b16 {%0,%1,%2,%3}, [%4];" \
                 : "=r"(r0), "=r"(r1), "=r"(r2), "=r"(r3) : "r"(addr))

#define LDSM4T(r0, r1, r2, r3, addr) \
    asm volatile("ldmatrix.sync.aligned.m8n8.x4.trans.shared.b16 {%0,%1,%2,%3}, [%4];" \
                 : "=r"(r0), "=r"(r1), "=r"(r2), "=r"(r3) : "r"(addr))

#define MMA16816(c, a0, a1, a2, a3, b0, b1) \
    asm volatile("mma.sync.aligned.m16n8k16.row.col.f32.bf16.bf16.f32 " \
                 "{%0,%1,%2,%3}, {%4,%5,%6,%7}, {%8,%9}, {%0,%1,%2,%3};" \
                 : "+f"((c)[0]), "+f"((c)[1]), "+f"((c)[2]), "+f"((c)[3]) \
                 : "r"(a0), "r"(a1), "r"(a2), "r"(a3), "r"(b0), "r"(b1))

__device__ int   g_starts[NB + 1];
__device__ float g_Q[NC * D];
__device__ float g_QtT[D * NC];      // [e][c] (fallback)
__device__ u32   g_QtbfH[NC * 128];  // pre-split bf16-hi Qt, k_main smem layout
__device__ u32   g_QtbfL[NC * 128];
__device__ float g_cK[NC];
__device__ float g_P[NB * NC * D];
__device__ float g_sumA[NB * NC];
__device__ float g_H[NB * NC * D];

__device__ __forceinline__ u32 s2u(const void* p) {
    u32 a;
    asm("{ .reg .u64 t; cvta.to.shared.u64 t, %1; cvt.u32.u64 %0, t; }" : "=r"(a) : "l"(p));
    return a;
}

__device__ __forceinline__ void split2(float v0, float v1, u32& hi, u32& lo) {
    CVTBF2(hi, v0, v1);
    float h0 = __uint_as_float(hi << 16);
    float h1 = __uint_as_float(hi & 0xffff0000u);
    CVTBF2(lo, v0 - h0, v1 - h1);
}

// ---------------- fused setup: meta + zero + Q + Qt + Qt bf16-split ----------------
__global__ __launch_bounds__(256) void k_setup(
    const void* __restrict__ batch, int n,
    const float* __restrict__ Qp,
    const float* __restrict__ Wq, const float* __restrict__ bq,
    const float* __restrict__ Wk, const float* __restrict__ bk) {
    __shared__ float shA[D];
    __shared__ float shQ[D];
    int c = blockIdx.x, e = threadIdx.x;

    // meta (block 0, threads < 64): dtype detect + lower_bound per graph
    if (c == 0 && e < NB + 1) {
        if (e < NB) {
            long long probe = ((const long long*)batch)[n / 4];
            int is32 = (probe < 0 || probe >= NB) ? 1 : 0;
            int lo = 0, hi = n;
            while (lo < hi) {
                int mid = (lo + hi) >> 1;
                long long bv = is32 ? (long long)((const int*)batch)[mid]
                                    : ((const long long*)batch)[mid];
                if (bv < (long long)e) lo = mid + 1; else hi = mid;
            }
            g_starts[e] = lo;
        } else {
            g_starts[NB] = n;
        }
    }

    // zero g_P slice (16384 floats/block) + g_sumA slice
    {
        float4* pz = (float4*)(g_P + (size_t)c * NC * D);
        float4 z = make_float4(0.f, 0.f, 0.f, 0.f);
        #pragma unroll
        for (int it = 0; it < 16; it++) pz[e + 256 * it] = z;
        if (e < NC) g_sumA[c * NC + e] = 0.f;
    }

    // Q[c][e] = Qp[c] . Wq[e] + bq[e]
    shA[e] = Qp[c * D + e];
    __syncthreads();
    {
        float a0 = 0.f, a1 = 0.f, a2 = 0.f, a3 = 0.f;
        #pragma unroll 4
        for (int k = 0; k < D; k += 4) {
            a0 = fmaf(shA[k + 0], Wq[e * D + k + 0], a0);
            a1 = fmaf(shA[k + 1], Wq[e * D + k + 1], a1);
            a2 = fmaf(shA[k + 2], Wq[e * D + k + 2], a2);
            a3 = fmaf(shA[k + 3], Wq[e * D + k + 3], a3);
        }
        float q = ((a0 + a1) + (a2 + a3)) + bq[e];
        shQ[e] = q;
        g_Q[c * D + e] = q;
    }
    __syncthreads();

    // Qt[c][e] = sum_d Q[c][d] * Wk[d][e]; cK[c] = Q[c].bk
    {
        float a0 = 0.f, a1 = 0.f;
        #pragma unroll 4
        for (int d = 0; d < D; d += 2) {
            a0 = fmaf(shQ[d + 0], Wk[(d + 0) * D + e], a0);
            a1 = fmaf(shQ[d + 1], Wk[(d + 1) * D + e], a1);
        }
        float v = a0 + a1;
        g_QtT[e * NC + c] = v;
        shA[e] = v;    // Qt row c into shared for split phase
        if (e == 0) {
            float ck = 0.f;
            for (int d = 0; d < D; d++) ck += shQ[d] * bk[d];
            g_cK[c] = ck;
        }
    }
    __syncthreads();

    // split Qt row -> g_QtbfH/L in k_main's swizzled layout
    if (e < 64) {
        int e4 = e;
        float v0 = shA[4 * e4 + 0], v1 = shA[4 * e4 + 1];
        float v2 = shA[4 * e4 + 2], v3 = shA[4 * e4 + 3];
        u32 h0, l0, h1, l1;
        split2(v0, v1, h0, l0);
        split2(v2, v3, h1, l1);
        int idx = c * 128 + ((2 * e4) ^ ((c & 7) << 2));
        g_QtbfH[idx] = h0; g_QtbfH[idx + 1] = h1;
        g_QtbfL[idx] = l0; g_QtbfL[idx + 1] = l1;
    }
}

// ---------------- mask + argout-tail-zero ----------------
__global__ void k_maskzero(float* __restrict__ maskout, float* __restrict__ argout,
                           int do_mask, int do_arg) {
    int idx = blockIdx.x * blockDim.x + threadIdx.x;
    if (idx >= NB * MAXN) return;
    int b = idx >> 12, pos = idx & (MAXN - 1);
    int cnt = g_starts[b + 1] - g_starts[b];
    if (do_mask) maskout[idx] = (pos < cnt) ? 1.f : 0.f;
    if (do_arg && pos >= cnt) argout[idx] = 0.f;
}

// ---------------- main fused kernel ----------------
// smem floats:
//   XnbfH [0,8192)      bf16-hi x [64n][256e], rows 512B, swz off^((n&7)<<4)
//   XnbfL [8192,16384)
//   QtbfH [16384,24576) bf16-hi Qt [64c][256e], rows 512B (cp.async from global)
//   QtbfL [24576,32768)
//   As    [32768,36864) f32 pair-swizzled [n][c]
//   AbfH  [36864,38912) | AbfL [38912,40960)
//   cKs 40960, sAcc 41024, flags 41088
//   raw   [41216, 57600) f32 staging (cp.async target)
#define SMEM_FLOATS 57600
extern __shared__ float smem[];

__global__ __launch_bounds__(NT, 1) void k_main(const float* __restrict__ x,
                                                float* __restrict__ argout, int has_arg) {
    float* As   = smem + 32768;
    float* cKs  = smem + 40960;
    float* sAcc = smem + 41024;
    int*   flagn = (int*)(smem + 41088);
    int*   flagl = (int*)(smem + 41089);
    float* rawF = smem + 41216;

    int t = threadIdx.x;
    int g = blockIdx.x / SPG, sl = blockIdx.x % SPG;
    int s0 = g_starts[g], s1 = g_starts[g + 1];
    int cnt = s1 - s0;
    int chunk = (cnt + SPG - 1) / SPG;
    int i0 = s0 + sl * chunk;
    int i1 = min(i0 + chunk, s1);
    if (i0 >= i1) return;  // uniform across block

    u32 sb = s2u(smem);
    const u32 xnH = sb, xnL = sb + 32768;
    const u32 qtH = sb + 65536, qtL = sb + 98304;
    const u32 abH = sb + 147456, abL = sb + 155648;
    const u32 rawU = sb + 41216u * 4u;

    // prologue: prefetch first tile + preconverted Qt (one cp.async group)
    {
        int nbj = min(TILE, i1 - i0);
        for (int r = t; r < nbj * 64; r += NT) {
            int n = r >> 6, e4 = r & 63;
            CP16(rawU + (u32)r * 16u, x + (size_t)(i0 + n) * D + 4 * e4);
        }
        for (int r = t; r < 2048; r += NT) {
            CP16(qtH + (u32)r * 16u, (const char*)g_QtbfH + (size_t)r * 16);
            CP16(qtL + (u32)r * 16u, (const char*)g_QtbfL + (size_t)r * 16);
        }
        CPCOMMIT();
    }

    // init: zero Xnbf, load cK
    for (int r = t; r < 16384; r += NT) ((u32*)smem)[r] = 0u;
    if (t < NC) { cKs[t] = g_cK[t]; sAcc[t] = 0.f; }
    if (t == 0) *flagn = 0;

    const int lane = t & 31;
    const int w    = t >> 5;            // 0..15

    // Phase-B MMA mapping
    const int cw = w & 3, nw = w >> 2;
    const int pb_arow = 16 * cw + (lane & 7) + 8 * ((lane >> 3) & 1);
    const int pb_ae   = (lane >> 4) & 1;
    const int pb_asw  = (pb_arow & 7) << 4;
    const int pb_brow = 16 * nw + (lane & 7) + 8 * ((lane >> 4) & 1);
    const int pb_be   = (lane >> 3) & 1;
    const int pb_bsw  = (pb_brow & 7) << 4;
    const int wo_c = 16 * cw + (lane >> 2);
    const int wo_n = 16 * nw + 2 * (lane & 3);

    // Phase-D mapping
    const int wr = w & 3, wc = w >> 2;
    const int a_row = 16 * wr + (lane & 7) + 8 * ((lane >> 3) & 1);
    const int a_hi = lane >> 4;
    const int a_sw = a_row & 7;
    const int pd_ksub = (lane & 7) + 8 * ((lane >> 3) & 1);
    const int pd_dh = (lane >> 4) & 1;

    // sumA mapping
    const int sa_c = (w < 8) ? (8 * w + (lane >> 2)) : 0;
    const int sa_q = lane & 3;

    float acc[8][4];
    #pragma unroll
    for (int nj = 0; nj < 8; nj++)
        #pragma unroll
        for (int q = 0; q < 4; q++) acc[nj][q] = 0.f;

    __syncthreads();

    for (int i = i0; i < i1; i += TILE) {
        int nb = min(TILE, i1 - i);

        // ---- wait prefetch, convert raw -> split bf16 Xnbf [n][e] ----
        CPWAIT0();
        __syncthreads();
        if (t == 0) *flagn = 0;
        for (int r = t; r < nb * 64; r += NT) {
            int n = r >> 6, e4 = r & 63;
            float4 v = *(const float4*)(rawF + (size_t)r * 4);
            u32 h0, l0, h1, l1;
            split2(v.x, v.y, h0, l0);
            split2(v.z, v.w, h1, l1);
            u32 off = n * 512 + ((e4 * 8) ^ ((n & 7) << 4));
            *(uint2*)((char*)smem + off)         = make_uint2(h0, h1);
            *(uint2*)((char*)smem + 32768 + off) = make_uint2(l0, l1);
        }
        __syncthreads();   // Xn ready AND raw fully consumed

        // ---- prefetch next tile (overlaps B/C/D) ----
        if (i + TILE < i1) {
            int j = i + TILE;
            int nbj = min(TILE, i1 - j);
            for (int r = t; r < nbj * 64; r += NT) {
                int n = r >> 6, e4 = r & 63;
                CP16(rawU + (u32)r * 16u, x + (size_t)(j + n) * D + 4 * e4);
            }
            CPCOMMIT();
        }

        // ---- Phase B (tensor): S[16c x 16n] per warp, k = 256 ----
        {
            float sc[4][4];
            #pragma unroll
            for (int p = 0; p < 4; p++)
                #pragma unroll
                for (int q = 0; q < 4; q++) sc[p][q] = 0.f;
            #pragma unroll
            for (int ks = 0; ks < 16; ks++) {
                const int pe = (ks & 1) * 2;
                u32 aoff = pb_arow * 512 + ((32 * ks + 16 * pb_ae) ^ pb_asw);
                u32 boff = pb_brow * 512 + ((32 * ks + 16 * pb_be) ^ pb_bsw);
                u32 ah0, ah1, ah2, ah3, al0, al1, al2, al3;
                u32 bh0, bh1, bh2, bh3, bl0, bl1, bl2, bl3;
                LDSM4(ah0, ah1, ah2, ah3, qtH + aoff);
                LDSM4(al0, al1, al2, al3, qtL + aoff);
                LDSM4(bh0, bh1, bh2, bh3, xnH + boff);
                LDSM4(bl0, bl1, bl2, bl3, xnL + boff);
                MMA16816(sc[pe],     ah0, ah1, ah2, ah3, bh0, bh1);
                MMA16816(sc[pe + 1], ah0, ah1, ah2, ah3, bh2, bh3);
                MMA16816(sc[pe],     al0, al1, al2, al3, bh0, bh1);
                MMA16816(sc[pe + 1], al0, al1, al2, al3, bh2, bh3);
                MMA16816(sc[pe],     ah0, ah1, ah2, ah3, bl0, bl1);
                MMA16816(sc[pe + 1], ah0, ah1, ah2, ah3, bl2, bl3);
            }
            float ck0 = cKs[wo_c], ck1 = cKs[wo_c + 8];
            #pragma unroll
            for (int h = 0; h < 2; h++) {
                float v0 = sc[h][0] + sc[h + 2][0];
                float v1 = sc[h][1] + sc[h + 2][1];
                float v2 = sc[h][2] + sc[h + 2][2];
                float v3 = sc[h][3] + sc[h + 2][3];
                int n0 = wo_n + 8 * h;
                int m0 = n0 & 31, m1 = (n0 + 1) & 31;
                As[n0 * 64 + 2 * ((wo_c >> 1) ^ m0) + (wo_c & 1)] = v0 + ck0;
                As[(n0 + 1) * 64 + 2 * ((wo_c >> 1) ^ m1) + (wo_c & 1)] = v1 + ck0;
                int c1 = wo_c + 8;
                As[n0 * 64 + 2 * ((c1 >> 1) ^ m0) + (c1 & 1)] = v2 + ck1;
                As[(n0 + 1) * 64 + 2 * ((c1 >> 1) ^ m1) + (c1 & 1)] = v3 + ck1;
            }
        }
        __syncthreads();

        // ---- Phase C: softmax + argmax, 2 nodes per warp interleaved ----
        #pragma unroll
        for (int r = 0; r < 2; r++) {
            int nA = 32 * r + w, nB = nA + 16;
            if (nA >= nb) break;
            bool aB = nB < nb;
            int mA_ = nA & 31, mB_ = nB & 31;
            int offA0 = nA * NC + 2 * ((lane >> 1) ^ mA_) + (lane & 1);
            int offA1 = nA * NC + 2 * (((lane >> 1) + 16) ^ mA_) + (lane & 1);
            int offB0 = nB * NC + 2 * ((lane >> 1) ^ mB_) + (lane & 1);
            int offB1 = nB * NC + 2 * (((lane >> 1) + 16) ^ mB_) + (lane & 1);
            float pA0 = As[offA0] * 0.0625f, pA1 = As[offA1] * 0.0625f;
            float pB0 = aB ? As[offB0] * 0.0625f : 0.f;
            float pB1 = aB ? As[offB1] * 0.0625f : 0.f;
            float mxA = fmaxf(pA0, pA1), mxB = fmaxf(pB0, pB1);
            #pragma unroll
            for (int off = 16; off; off >>= 1) {
                mxA = fmaxf(mxA, __shfl_xor_sync(0xffffffffu, mxA, off));
                mxB = fmaxf(mxB, __shfl_xor_sync(0xffffffffu, mxB, off));
            }
            float eA0 = __expf(pA0 - mxA), eA1 = __expf(pA1 - mxA);
            float eB0 = __expf(pB0 - mxB), eB1 = __expf(pB1 - mxB);
            float zA = eA0 + eA1, zB = eB0 + eB1;
            #pragma unroll
            for (int off = 16; off; off >>= 1) {
                zA += __shfl_xor_sync(0xffffffffu, zA, off);
                zB += __shfl_xor_sync(0xffffffffu, zB, off);
            }
            float rzA = __fdividef(1.f, zA), rzB = __fdividef(1.f, zB);
            float avA0 = eA0 * rzA, avA1 = eA1 * rzA;
            float avB0 = eB0 * rzB, avB1 = eB1 * rzB;
            float bvA; int biA;
            if (avA0 >= avA1) { bvA = avA0; biA = lane; } else { bvA = avA1; biA = lane + 32; }
            float bvB; int biB;
            if (avB0 >= avB1) { bvB = avB0; biB = lane; } else { bvB = avB1; biB = lane + 32; }
            #pragma unroll
            for (int off = 16; off; off >>= 1) {
                float ovA = __shfl_xor_sync(0xffffffffu, bvA, off);
                int   oiA = __shfl_xor_sync(0xffffffffu, biA, off);
                float ovB = __shfl_xor_sync(0xffffffffu, bvB, off);
                int   oiB = __shfl_xor_sync(0xffffffffu, biB, off);
                if (ovA > bvA || (ovA == bvA && oiA < biA)) { bvA = ovA; biA = oiA; }
                if (ovB > bvB || (ovB == bvB && oiB < biB)) { bvB = ovB; biB = oiB; }
            }
            As[offA0] = avA0;
            As[offA1] = avA1;
            if (aB) { As[offB0] = avB0; As[offB1] = avB1; }
            float xA0 = (biA == lane) ? -1e30f : avA0;
            float xA1 = (biA == lane + 32) ? -1e30f : avA1;
            float xB0 = (biB == lane) ? -1e30f : avB0;
            float xB1 = (biB == lane + 32) ? -1e30f : avB1;
            float m2A = fmaxf(xA0, xA1), m2B = fmaxf(xB0, xB1);
            #pragma unroll
            for (int off = 16; off; off >>= 1) {
                m2A = fmaxf(m2A, __shfl_xor_sync(0xffffffffu, m2A, off));
                m2B = fmaxf(m2B, __shfl_xor_sync(0xffffffffu, m2B, off));
            }
            if (lane == 0) {
                if (has_arg) {
                    int posA = (i + nA) - s0;
                    argout[(size_t)g * MAXN + posA] = (float)biA;
                    if (aB) {
                        int posB = (i + nB) - s0;
                        argout[(size_t)g * MAXN + posB] = (float)biB;
                    }
                }
                if (bvA - m2A < FLAG_EPS) { int k = atomicAdd(flagn, 1); flagl[k] = nA; }
                if (aB && (bvB - m2B < FLAG_EPS)) { int k = atomicAdd(flagn, 1); flagl[k] = nB; }
            }
        }
        __syncthreads();

        // ---- fallback: exact argmax for flagged nodes (rare) ----
        int nf = *flagn;
        if (has_arg) {
            for (int f = w; f < nf; f += 16) {
                int node = flagl[f];
                const float* xr = x + (size_t)(i + node) * D;
                float fs0 = 0.f, fs1 = 0.f;
                for (int e = 0; e < D; e++) {
                    float xe = __ldg(xr + e);
                    float2 q = *(const float2*)(g_QtT + e * NC + 2 * lane);
                    fs0 = fmaf(xe, q.x, fs0);
                    fs1 = fmaf(xe, q.y, fs1);
                }
                fs0 += cKs[2 * lane];
                fs1 += cKs[2 * lane + 1];
                float p0 = fs0 * 0.0625f, p1 = fs1 * 0.0625f;
                float mx = fmaxf(p0, p1);
                #pragma unroll
                for (int off = 16; off; off >>= 1)
                    mx = fmaxf(mx, __shfl_xor_sync(0xffffffffu, mx, off));
                float e0 = expf(p0 - mx), e1 = expf(p1 - mx);
                float z = e0 + e1;
                #pragma unroll
                for (int off = 16; off; off >>= 1)
                    z += __shfl_xor_sync(0xffffffffu, z, off);
                float av0 = e0 / z, av1 = e1 / z;
                float bv; int bi;
                if (av0 >= av1) { bv = av0; bi = 2 * lane; } else { bv = av1; bi = 2 * lane + 1; }
                #pragma unroll
                for (int off = 16; off; off >>= 1) {
                    float ov = __shfl_xor_sync(0xffffffffu, bv, off);
                    int   oi = __shfl_xor_sync(0xffffffffu, bi, off);
                    if (ov > bv || (ov == bv && oi < bi)) { bv = ov; bi = oi; }
                }
                if (lane == 0) {
                    int pos = (i + node) - s0;
                    argout[(size_t)g * MAXN + pos] = (float)bi;
                }
            }
        }

        // ---- sumA: warps 0..7, 4 lanes per cluster x 16 nodes each ----
        if (w < 8) {
            int c = sa_c;
            int gidx = c >> 1, par = c & 1;
            float sa = 0.f;
            int nlo = sa_q * 16, nhi = min(nlo + 16, nb);
            for (int n = nlo; n < nhi; n++)
                sa += As[n * NC + 2 * (gidx ^ (n & 31)) + par];
            sa += __shfl_xor_sync(0xffffffffu, sa, 1);
            sa += __shfl_xor_sync(0xffffffffu, sa, 2);
            if (sa_q == 0) sAcc[c] += sa;
        }

        // ---- convert A -> AbfH/AbfL ([c][n], rows 128B SW128) ----
        {
            int c = t >> 3, n0 = (t & 7) * 8;
            u32 ph[4], pl[4];
            #pragma unroll
            for (int q = 0; q < 4; q++) {
                int na = n0 + 2 * q, nb2 = na + 1;
                float va = (na < nb)  ? As[na * NC + 2 * ((c >> 1) ^ (na & 31)) + (c & 1)] : 0.f;
                float vb = (nb2 < nb) ? As[nb2 * NC + 2 * ((c >> 1) ^ (nb2 & 31)) + (c & 1)] : 0.f;
                split2(va, vb, ph[q], pl[q]);
            }
            u32 so = (c * 128 + n0 * 2);
            so = so ^ ((so >> 3) & 0x70);
            *(uint4*)((char*)smem + (abH - sb) + so) = make_uint4(ph[0], ph[1], ph[2], ph[3]);
            *(uint4*)((char*)smem + (abL - sb) + so) = make_uint4(pl[0], pl[1], pl[2], pl[3]);
        }
        __syncthreads();

        // ---- Phase D (tensor): acc += A[c][n] * X[n][d] ----
        #pragma unroll
        for (int ks = 0; ks < 4; ks++) {
            u32 a_off = (a_row << 7) + (((2 * ks + a_hi) ^ a_sw) << 4);
            u32 ah0, ah1, ah2, ah3, al0, al1, al2, al3;
            LDSM4(ah0, ah1, ah2, ah3, abH + a_off);
            LDSM4(al0, al1, al2, al3, abL + a_off);
            int k_row = 16 * ks + pd_ksub;
            u32 bbase = k_row * 512;
            u32 bsw = (k_row & 7) << 4;
            #pragma unroll
            for (int jj = 0; jj < 4; jj++) {
                u32 b_off = bbase + ((128 * wc + 32 * jj + 16 * pd_dh) ^ bsw);
                u32 bh0, bh1, bh2, bh3, bl0, bl1, bl2, bl3;
                LDSM4T(bh0, bh1, bh2, bh3, xnH + b_off);
                LDSM4T(bl0, bl1, bl2, bl3, xnL + b_off);
                MMA16816(acc[2 * jj],     ah0, ah1, ah2, ah3, bh0, bh1);
                MMA16816(acc[2 * jj + 1], ah0, ah1, ah2, ah3, bh2, bh3);
                MMA16816(acc[2 * jj],     al0, al1, al2, al3, bh0, bh1);
                MMA16816(acc[2 * jj + 1], al0, al1, al2, al3, bh2, bh3);
                MMA16816(acc[2 * jj],     ah0, ah1, ah2, ah3, bl0, bl1);
                MMA16816(acc[2 * jj + 1], ah0, ah1, ah2, ah3, bl2, bl3);
            }
        }
        __syncthreads();
    }

    // ---- flush accumulators ----
    {
        float* pgb = g_P + (size_t)g * NC * D;
        int r0 = 16 * wr + (lane >> 2);
        #pragma unroll
        for (int nj = 0; nj < 8; nj++) {
            int col = 64 * wc + 8 * nj + 2 * (lane & 3);
            atomicAdd(pgb + (size_t)r0 * D + col,           acc[nj][0]);
            atomicAdd(pgb + (size_t)r0 * D + col + 1,       acc[nj][1]);
            atomicAdd(pgb + (size_t)(r0 + 8) * D + col,     acc[nj][2]);
            atomicAdd(pgb + (size_t)(r0 + 8) * D + col + 1, acc[nj][3]);
        }
    }
    if (t < NC) atomicAdd(&g_sumA[g * NC + t], sAcc[t]);
}

// ---------------- epilogue GEMMs: register-tiled f32x2 ----------------
#define ASTR 34
template <int MODE>
__global__ __launch_bounds__(256) void k_gemm(const float* __restrict__ Bmat,
                                              const float* __restrict__ bias,
                                              float* __restrict__ Cout) {
    __shared__ float Ash[D * ASTR];
    int t = threadIdx.x;
    int tx = t & 127, ty = t >> 7;
    int r0 = blockIdx.x * 32;
    const float* Amat = (MODE == 0) ? g_P : g_H;

    {   // stage A [32r][256k] -> Ash[k][r]
        int row = t >> 3, k4 = (t & 7) * 4;
        const float* src = Amat + (size_t)(r0 + row) * D + k4;
        #pragma unroll
        for (int it = 0; it < 8; it++) {
            float4 v = *(const float4*)(src + 32 * it);
            int kb = k4 + 32 * it;
            Ash[(kb + 0) * ASTR + row] = v.x;
            Ash[(kb + 1) * ASTR + row] = v.y;
            Ash[(kb + 2) * ASTR + row] = v.z;
            Ash[(kb + 3) * ASTR + row] = v.w;
        }
    }
    __syncthreads();

    int q0 = 2 * tx;
    int rbase = 16 * ty;
    ull acc2[8][2];
    #pragma unroll
    for (int p = 0; p < 8; p++) { acc2[p][0] = 0ull; acc2[p][1] = 0ull; }

    const float* b0p = Bmat + (size_t)q0 * D;
    const float* b1p = Bmat + (size_t)(q0 + 1) * D;
    for (int k = 0; k < D; k += 4) {
        float4 bv0 = *(const float4*)(b0p + k);
        float4 bv1 = *(const float4*)(b1p + k);
        float b0s[4] = {bv0.x, bv0.y, bv0.z, bv0.w};
        float b1s[4] = {bv1.x, bv1.y, bv1.z, bv1.w};
        #pragma unroll
        for (int kk = 0; kk < 4; kk++) {
            ull bd0, bd1;
            DUP(bd0, b0s[kk]);
            DUP(bd1, b1s[kk]);
            const ull* ar = (const ull*)(Ash + (k + kk) * ASTR + rbase);
            #pragma unroll
            for (int p = 0; p < 8; p++) {
                ull av = ar[p];
                FMA2(acc2[p][0], av, bd0);
                FMA2(acc2[p][1], av, bd1);
            }
        }
    }

    float bias0 = bias[q0], bias1 = bias[q0 + 1];
    #pragma unroll
    for (int p = 0; p < 8; p++) {
        int r = r0 + rbase + 2 * p;
        float v00 = __uint_as_float((u32)(acc2[p][0] & 0xffffffffull));
        float v01 = __uint_as_float((u32)(acc2[p][1] & 0xffffffffull));
        float v10 = __uint_as_float((u32)(acc2[p][0] >> 32));
        float v11 = __uint_as_float((u32)(acc2[p][1] >> 32));
        if (MODE == 0) {
            int c0 = r & (NC - 1), c1 = (r + 1) & (NC - 1);
            float sa0 = g_sumA[r], sa1 = g_sumA[r + 1];
            v00 += g_Q[c0 * D + q0]     + sa0 * bias0;
            v01 += g_Q[c0 * D + q0 + 1] + sa0 * bias1;
            v10 += g_Q[c1 * D + q0]     + sa1 * bias0;
            v11 += g_Q[c1 * D + q0 + 1] + sa1 * bias1;
            *(float2*)(g_H + (size_t)r * D + q0)       = make_float2(v00, v01);
            *(float2*)(g_H + (size_t)(r + 1) * D + q0) = make_float2(v10, v11);
        } else {
            v00 = fmaxf(v00 + bias0, 0.f);
            v01 = fmaxf(v01 + bias1, 0.f);
            v10 = fmaxf(v10 + bias0, 0.f);
            v11 = fmaxf(v11 + bias1, 0.f);
            *(float2*)(Cout + (size_t)r * D + q0)       = make_float2(v00, v01);
            *(float2*)(Cout + (size_t)(r + 1) * D + q0) = make_float2(v10, v11);
        }
    }
}

extern "C" void kernel_launch(void* const* d_in, const int* in_sizes, int n_in,
                              void* d_out, int out_size) {
    const float* x    = (const float*)d_in[0];
    const void*  bat  = d_in[1];
    const float* Qp   = (const float*)d_in[2];
    const float* WQ_w = (const float*)d_in[3];
    const float* WQ_b = (const float*)d_in[4];
    const float* WK_w = (const float*)d_in[5];
    const float* WK_b = (const float*)d_in[6];
    const float* WV_w = (const float*)d_in[7];
    const float* WV_b = (const float*)d_in[8];
    const float* WO_w = (const float*)d_in[9];
    const float* WO_b = (const float*)d_in[10];
    (void)n_in;

    int n_nodes = in_sizes[0] / D;
    float* out = (float*)d_out;
    int has_arg  = out_size >= (NB * NC * D + NB * MAXN);
    int has_mask = out_size >= (NB * NC * D + 2 * NB * MAXN);
    float* argout  = out + NB * NC * D;
    float* maskout = argout + NB * MAXN;

    k_setup<<<NC, 256>>>(bat, n_nodes, Qp, WQ_w, WQ_b, WK_w, WK_b);
    if (has_arg || has_mask)
        k_maskzero<<<(NB * MAXN) / 256, 256>>>(maskout, argout, has_mask, has_arg);

    const int smem_main = SMEM_FLOATS * (int)sizeof(float);
    cudaFuncSetAttribute(k_main, cudaFuncAttributeMaxDynamicSharedMemorySize, smem_main);
    k_main<<<NB * SPG, NT, smem_main>>>(x, argout, has_arg);

    k_gemm<0><<<(NB * NC) / 32, 256>>>(WV_w, WV_b, nullptr);
    k_gemm<1><<<(NB * NC) / 32, 256>>>(WO_w, WO_b, out);
}